// round 3
// baseline (speedup 1.0000x reference)
#include <cuda_runtime.h>
#include <math.h>
#include <stdint.h>

#define NN 262144
#define DD 16
#define KK 64
#define TAUF 0.1f
#define DLOG2PI 1.8378770664093454835
#define L2E 1.4426950408889634f
#define LN2 0.6931471805599453f

#define MAIN_GRID 1024
#define MAIN_BLOCK 256
#define WARPS_PER_BLOCK 8
#define MM_GRID 2048

// ---------------- device globals (no dynamic allocation) ----------------
__device__ float g_w[KK][DD];     // log2e * exp(-r_k) * mu_k[d]
__device__ float g_alpha2[KK];    // log2e * (-0.5*exp(-r_k))
__device__ float g_cc2[KK];       // log2e * (alpha*||mu_k||^2 + beta_k)
__device__ float g_logpi[KK];     // natural log_softmax(pi)
__device__ float g_logpi2[KK];    // log2e * logpi
__device__ float g_sumlogpi;
__device__ unsigned g_minkey[DD];
__device__ unsigned g_maxkey[DD];
__device__ float g_partial[MAIN_GRID];

// ---------------- helpers ----------------
__device__ __forceinline__ unsigned fkey(float f) {
    unsigned u = __float_as_uint(f);
    return (u & 0x80000000u) ? ~u : (u | 0x80000000u);
}
__device__ __forceinline__ float fdec(unsigned k) {
    unsigned u = (k & 0x80000000u) ? (k & 0x7FFFFFFFu) : ~k;
    return __uint_as_float(u);
}

// ---------------- kernel 1: per-k constants + logpi + minmax init ----------------
__global__ void prep_kernel(const float* __restrict__ mu,
                            const float* __restrict__ pi,
                            const float* __restrict__ rv) {
    __shared__ float sh[KK];
    int t = threadIdx.x;          // 64 threads
    float p = pi[t];
    sh[t] = p; __syncthreads();
    for (int s = 32; s; s >>= 1) { if (t < s) sh[t] = fmaxf(sh[t], sh[t + s]); __syncthreads(); }
    float m = sh[0]; __syncthreads();
    sh[t] = __expf(p - m); __syncthreads();
    for (int s = 32; s; s >>= 1) { if (t < s) sh[t] += sh[t + s]; __syncthreads(); }
    float lse = m + __logf(sh[0]); __syncthreads();
    float lp = p - lse;
    g_logpi[t]  = lp;
    g_logpi2[t] = lp * L2E;
    sh[t] = lp; __syncthreads();
    for (int s = 32; s; s >>= 1) { if (t < s) sh[t] += sh[t + s]; __syncthreads(); }
    if (t == 0) g_sumlogpi = sh[0];

    float rk = rv[t];
    float ie = __expf(-rk);               // 1/exp(r_k)
    float msq = 0.f;
#pragma unroll
    for (int d = 0; d < DD; d++) {
        float md = mu[t * DD + d];
        g_w[t][d] = L2E * ie * md;
        msq = fmaf(md, md, msq);
    }
    float alpha = -0.5f * ie;
    float beta  = -0.5f * 16.f * (rk + (float)DLOG2PI);
    g_alpha2[t] = L2E * alpha;
    g_cc2[t]    = L2E * fmaf(alpha, msq, beta);

    if (t < DD) { g_minkey[t] = 0xFFFFFFFFu; g_maxkey[t] = 0u; }
}

// ---------------- kernel 2: per-dim min/max of met_locs ----------------
__global__ void __launch_bounds__(256) minmax_kernel(const float4* __restrict__ met4) {
    const int n4 = NN * DD / 4;
    int t = blockIdx.x * blockDim.x + threadIdx.x;
    int stride = gridDim.x * blockDim.x;      // multiple of 4 -> phase fixed
    float4 mn = make_float4(3.4e38f, 3.4e38f, 3.4e38f, 3.4e38f);
    float4 mx = make_float4(-3.4e38f, -3.4e38f, -3.4e38f, -3.4e38f);
    for (int i = t; i < n4; i += stride) {
        float4 v = met4[i];
        mn.x = fminf(mn.x, v.x); mx.x = fmaxf(mx.x, v.x);
        mn.y = fminf(mn.y, v.y); mx.y = fmaxf(mx.y, v.y);
        mn.z = fminf(mn.z, v.z); mx.z = fmaxf(mx.z, v.z);
        mn.w = fminf(mn.w, v.w); mx.w = fmaxf(mx.w, v.w);
    }
    int d0 = (t & 3) * 4;
    atomicMin(&g_minkey[d0 + 0], fkey(mn.x)); atomicMax(&g_maxkey[d0 + 0], fkey(mx.x));
    atomicMin(&g_minkey[d0 + 1], fkey(mn.y)); atomicMax(&g_maxkey[d0 + 1], fkey(mx.y));
    atomicMin(&g_minkey[d0 + 2], fkey(mn.z)); atomicMax(&g_maxkey[d0 + 2], fkey(mx.z));
    atomicMin(&g_minkey[d0 + 3], fkey(mn.w)); atomicMax(&g_maxkey[d0 + 3], fkey(mx.w));
}

// ---------------- kernel 3: z-loss (warp per row, lane owns k=2l,2l+1) ----------------
__global__ void __launch_bounds__(MAIN_BLOCK) zloss_kernel(const float* __restrict__ met,
                                                           const float* __restrict__ z) {
    const int lane = threadIdx.x & 31;
    const int warp = threadIdx.x >> 5;
    const int gwarp = blockIdx.x * WARPS_PER_BLOCK + warp;
    const int totw = MAIN_GRID * WARPS_PER_BLOCK;

    const int k0 = 2 * lane;
    float w0[DD], w1[DD];
#pragma unroll
    for (int d = 0; d < DD; d++) { w0[d] = g_w[k0][d]; w1[d] = g_w[k0 + 1][d]; }
    const float a0 = g_alpha2[k0], a1 = g_alpha2[k0 + 1];
    const float c0 = g_cc2[k0],    c1 = g_cc2[k0 + 1];
    const float lp0 = g_logpi2[k0], lp1 = g_logpi2[k0 + 1];

    float accT = 0.f;     // lane 0 only: sum of nonlinear per-row terms (natural log units)
    float acc_sz = 0.f;   // per-lane: sum of raw z (linear term, deferred reduce)

    for (int row = gwarp; row < NN; row += totw) {
        const float4* xp = reinterpret_cast<const float4*>(met + (size_t)row * DD);
        float4 qa = xp[0], qb = xp[1], qc = xp[2], qd = xp[3];
        float x[DD] = { qa.x, qa.y, qa.z, qa.w, qb.x, qb.y, qb.z, qb.w,
                        qc.x, qc.y, qc.z, qc.w, qd.x, qd.y, qd.z, qd.w };
        const float2 zz = *reinterpret_cast<const float2*>(z + (size_t)row * KK + 2 * lane);

        float d0 = c0, d1 = c1, xs = 0.f;
#pragma unroll
        for (int d = 0; d < DD; d++) {
            d0 = fmaf(x[d], w0[d], d0);
            d1 = fmaf(x[d], w1[d], d1);
            xs = fmaf(x[d], x[d], xs);
        }
        float l0 = fmaf(a0, xs, d0);      // logN_k in log2 units
        float l1 = fmaf(a1, xs, d1);

        float z0 = zz.x, z1 = zz.y;
        float z02 = z0 * L2E, z12 = z1 * L2E;
        float v0 = z02 + l0, v1 = z12 + l1;
        float u0 = fmaf(-TAUF, z02, lp0), u1 = fmaf(-TAUF, z12, lp1);

        float mz = fmaxf(z02, z12);
        float mv = fmaxf(v0, v1);
        float mq = fmaxf(u0, u1);
#pragma unroll
        for (int off = 16; off; off >>= 1) {
            mz = fmaxf(mz, __shfl_xor_sync(0xffffffffu, mz, off));
            mv = fmaxf(mv, __shfl_xor_sync(0xffffffffu, mv, off));
            mq = fmaxf(mq, __shfl_xor_sync(0xffffffffu, mq, off));
        }

        float ez = exp2f(z02 - mz) + exp2f(z12 - mz);
        float ev = exp2f(v0 - mv) + exp2f(v1 - mv);
        float eu = exp2f(u0 - mq) + exp2f(u1 - mq);
#pragma unroll
        for (int off = 16; off; off >>= 1) {
            ez += __shfl_xor_sync(0xffffffffu, ez, off);
            ev += __shfl_xor_sync(0xffffffffu, ev, off);
            eu += __shfl_xor_sync(0xffffffffu, eu, off);
        }
        acc_sz += z0 + z1;

        if (lane == 0) {
            float lz = mz + __log2f(ez);   // lse_z / ln2
            float lv = mv + __log2f(ev);   // lse(z+logN) / ln2
            float lu = mq + __log2f(eu);   // lse(logpi - tau z) / ln2
            accT += LN2 * fmaf(63.f, lz, fmaf(-64.f, lu, lv));
        }
    }

#pragma unroll
    for (int off = 16; off; off >>= 1)
        acc_sz += __shfl_xor_sync(0xffffffffu, acc_sz, off);

    __shared__ float sred[WARPS_PER_BLOCK];
    if (lane == 0) sred[warp] = fmaf(-(TAUF + 1.f), acc_sz, accT);
    __syncthreads();
    if (threadIdx.x == 0) {
        float s = 0.f;
#pragma unroll
        for (int i = 0; i < WARPS_PER_BLOCK; i++) s += sred[i];
        g_partial[blockIdx.x] = s;
    }
}

// ---------------- kernel 4: small losses + final sum (double) ----------------
__global__ void final_kernel(const float* __restrict__ mu,
                             const float* __restrict__ lambda_mu,
                             const float* __restrict__ b,
                             const float* __restrict__ Cv,
                             const float* __restrict__ rv,
                             float* __restrict__ out) {
    __shared__ float shR[DD];
    __shared__ double sred[256];
    int t = threadIdx.x;
    if (t < DD) shR[t] = fdec(g_maxkey[t]) - fdec(g_minkey[t]);
    __syncthreads();

    double R2 = 0.0;
#pragma unroll
    for (int d = 0; d < DD; d++) R2 += (double)shR[d] * (double)shR[d];
    const double cc = 5.0, gg = 4.0;                 // c = 1.25+15/4, g = 0.25+15/4
    const double G  = cc / (50.0 * gg) * sqrt(R2);

    double acc = 0.0;
    // mu quadratic + b quadratic over K*D
    for (int i = t; i < KK * DD; i += blockDim.x) {
        int d = i & (DD - 1);
        double lam = (double)lambda_mu[d];
        double var = lam * lam * (double)shR[d];
        double diff = (double)mu[i] - (double)b[i];
        double bb = (double)b[i];
        acc += 0.5 * diff * diff / var + 0.5 * bb * bb;
    }
    // per-dim: mu logdet (K/2 * log var each) + lambda prior
    for (int d = t; d < DD; d += blockDim.x) {
        double lam = (double)lambda_mu[d];
        double var = lam * lam * (double)shR[d];
        acc += 0.5 * (double)KK * log(var);
        acc -= 0.5 * log(0.5) - lgamma(0.5) - 0.5 * lam - 0.5 * exp(lam);
    }
    // per-k: r prior (Gamma(c, rate=C)) + C prior (Gamma(g, rate=G))
    for (int k = t; k < KK; k += blockDim.x) {
        double rk = (double)rv[k], Ck = (double)Cv[k];
        acc -= cc * log(Ck) - (cc - 1.0) * rk - Ck * exp(-rk) - lgamma(cc);
        acc -= gg * log(G)  - (gg - 1.0) * Ck - G  * exp(-Ck) - lgamma(gg);
    }
    // z-loss partials
    for (int i = t; i < MAIN_GRID; i += blockDim.x) acc -= (double)g_partial[i];

    if (t == 0) {
        double sumlp = (double)g_sumlogpi;
        double G0 = lgamma(64.0) + 63.0 * log(0.1) + sumlp;   // per-row constant in con
        acc -= (double)NN * G0;                               // z-loss constant part
        acc += (63.0 / 64.0) * sumlp;                         // pi_loss
        acc += (double)KK * 0.5 * (double)DD * DLOG2PI;       // mu_loss const
        acc += 0.5 * (double)KK * (double)DD * DLOG2PI;       // b_loss const
    }

    sred[t] = acc; __syncthreads();
    for (int s = 128; s; s >>= 1) { if (t < s) sred[t] += sred[t + s]; __syncthreads(); }
    if (t == 0) out[0] = (float)sred[0];
}

// ---------------- launch ----------------
extern "C" void kernel_launch(void* const* d_in, const int* in_sizes, int n_in,
                              void* d_out, int out_size) {
    const float* met = (const float*)d_in[0];
    const float* mu  = (const float*)d_in[1];
    const float* pi  = (const float*)d_in[2];
    const float* lam = (const float*)d_in[3];
    const float* b   = (const float*)d_in[4];
    const float* C   = (const float*)d_in[5];
    const float* r   = (const float*)d_in[6];
    const float* z   = (const float*)d_in[7];
    (void)in_sizes; (void)n_in; (void)out_size;

    prep_kernel<<<1, 64>>>(mu, pi, r);
    minmax_kernel<<<MM_GRID, 256>>>(reinterpret_cast<const float4*>(met));
    zloss_kernel<<<MAIN_GRID, MAIN_BLOCK>>>(met, z);
    final_kernel<<<1, 256>>>(mu, lam, b, C, r, (float*)d_out);
}

// round 4
// speedup vs baseline: 5.4838x; 5.4838x over previous
#include <cuda_runtime.h>
#include <math.h>
#include <stdint.h>

#define NN 262144
#define DD 16
#define KK 64
#define TAUF 0.1f
#define DLOG2PI 1.8378770664093454835
#define L2E 1.4426950408889634f
#define LN2 0.6931471805599453f

#define ZBLK 128
#define ZGRID (NN / ZBLK)   // 2048

// ---------------- device globals ----------------
__device__ float g_w[KK][DD];     // log2e * exp(-r_k) * mu_k[d]
__device__ float g_alpha2[KK];    // log2e * (-0.5*exp(-r_k))
__device__ float g_cc2[KK];       // log2e * (alpha*||mu_k||^2 + beta_k)
__device__ float g_logpi2[KK];    // log2e * log_softmax(pi)
__device__ float g_sumlogpi;
__device__ unsigned g_minkey[DD];
__device__ unsigned g_maxkey[DD];
__device__ float g_partial[ZGRID];

// ---------------- helpers ----------------
__device__ __forceinline__ unsigned fkey(float f) {
    unsigned u = __float_as_uint(f);
    return (u & 0x80000000u) ? ~u : (u | 0x80000000u);
}
__device__ __forceinline__ float fdec(unsigned k) {
    unsigned u = (k & 0x80000000u) ? (k & 0x7FFFFFFFu) : ~k;
    return __uint_as_float(u);
}
__device__ __forceinline__ float ex2f(float x) {
    float y; asm("ex2.approx.f32 %0, %1;" : "=f"(y) : "f"(x)); return y;
}
__device__ __forceinline__ float lg2f(float x) {
    float y; asm("lg2.approx.f32 %0, %1;" : "=f"(y) : "f"(x)); return y;
}

// ---------------- kernel 1: per-k constants + logpi + minmax init ----------------
__global__ void prep_kernel(const float* __restrict__ mu,
                            const float* __restrict__ pi,
                            const float* __restrict__ rv) {
    __shared__ float sh[KK];
    int t = threadIdx.x;          // 64 threads
    float p = pi[t];
    sh[t] = p; __syncthreads();
    for (int s = 32; s; s >>= 1) { if (t < s) sh[t] = fmaxf(sh[t], sh[t + s]); __syncthreads(); }
    float m = sh[0]; __syncthreads();
    sh[t] = __expf(p - m); __syncthreads();
    for (int s = 32; s; s >>= 1) { if (t < s) sh[t] += sh[t + s]; __syncthreads(); }
    float lse = m + __logf(sh[0]); __syncthreads();
    float lp = p - lse;
    g_logpi2[t] = lp * L2E;
    sh[t] = lp; __syncthreads();
    for (int s = 32; s; s >>= 1) { if (t < s) sh[t] += sh[t + s]; __syncthreads(); }
    if (t == 0) g_sumlogpi = sh[0];

    float rk = rv[t];
    float ie = __expf(-rk);               // 1/exp(r_k)
    float msq = 0.f;
#pragma unroll
    for (int d = 0; d < DD; d++) {
        float md = mu[t * DD + d];
        g_w[t][d] = L2E * ie * md;
        msq = fmaf(md, md, msq);
    }
    float alpha = -0.5f * ie;
    float beta  = -0.5f * 16.f * (rk + (float)DLOG2PI);
    g_alpha2[t] = L2E * alpha;
    g_cc2[t]    = L2E * fmaf(alpha, msq, beta);

    if (t < DD) { g_minkey[t] = 0xFFFFFFFFu; g_maxkey[t] = 0u; }
}

// ---------------- kernel 2: z-loss, thread-per-row, no shuffles in hot path ----------------
__global__ void __launch_bounds__(ZBLK) zloss_kernel(const float* __restrict__ met,
                                                     const float* __restrict__ z) {
    __shared__ float4 sw4[KK * 4];             // 4KB  (w rows as float4)
    __shared__ float sA[KK], sC[KK], sP[KK];   // 768B
    __shared__ float sv[KK][ZBLK];             // 32KB (v_k per thread, conflict-free)
    __shared__ float sred[ZBLK / 32];

    const int t = threadIdx.x;
    const int lane = t & 31;

    if (t < KK) { sA[t] = g_alpha2[t]; sC[t] = g_cc2[t]; sP[t] = g_logpi2[t]; }
    const float4* gw4 = reinterpret_cast<const float4*>(&g_w[0][0]);
    for (int i = t; i < KK * 4; i += ZBLK) sw4[i] = gw4[i];
    __syncthreads();

    const int row = blockIdx.x * ZBLK + t;
    const float4* xp = reinterpret_cast<const float4*>(met + (size_t)row * DD);
    float4 qa = xp[0], qb = xp[1], qc = xp[2], qd = xp[3];
    float x[DD] = { qa.x, qa.y, qa.z, qa.w, qb.x, qb.y, qb.z, qb.w,
                    qc.x, qc.y, qc.z, qc.w, qd.x, qd.y, qd.z, qd.w };
    float xs = 0.f;
#pragma unroll
    for (int d = 0; d < DD; d++) xs = fmaf(x[d], x[d], xs);

    const float4* zp = reinterpret_cast<const float4*>(z + (size_t)row * KK);

    float mz = -3.4e38f, mv = -3.4e38f, mq = -3.4e38f, sz = 0.f;

#define P1(k, zn) do {                                                    \
        const float4 wa = sw4[4*(k)+0], wb = sw4[4*(k)+1];                \
        const float4 wc = sw4[4*(k)+2], wd = sw4[4*(k)+3];                \
        float a1 = fmaf(sA[k], xs, sC[k]);                                \
        float a2 = 0.f;                                                   \
        a1 = fmaf(x[0], wa.x, a1);  a2 = fmaf(x[1], wa.y, a2);            \
        a1 = fmaf(x[2], wa.z, a1);  a2 = fmaf(x[3], wa.w, a2);            \
        a1 = fmaf(x[4], wb.x, a1);  a2 = fmaf(x[5], wb.y, a2);            \
        a1 = fmaf(x[6], wb.z, a1);  a2 = fmaf(x[7], wb.w, a2);            \
        a1 = fmaf(x[8], wc.x, a1);  a2 = fmaf(x[9], wc.y, a2);            \
        a1 = fmaf(x[10], wc.z, a1); a2 = fmaf(x[11], wc.w, a2);           \
        a1 = fmaf(x[12], wd.x, a1); a2 = fmaf(x[13], wd.y, a2);           \
        a1 = fmaf(x[14], wd.z, a1); a2 = fmaf(x[15], wd.w, a2);           \
        float z2 = (zn) * L2E;                                            \
        float v = z2 + a1 + a2;                                           \
        sv[k][t] = v;                                                     \
        mv = fmaxf(mv, v);                                                \
        mz = fmaxf(mz, z2);                                               \
        mq = fmaxf(mq, fmaf(-TAUF, z2, sP[k]));                           \
        sz += (zn);                                                       \
    } while (0)

#pragma unroll 4
    for (int kg = 0; kg < 16; kg++) {
        float4 zq = zp[kg];
        P1(4 * kg + 0, zq.x);
        P1(4 * kg + 1, zq.y);
        P1(4 * kg + 2, zq.z);
        P1(4 * kg + 3, zq.w);
    }
#undef P1

    float ez = 0.f, ev = 0.f, eu = 0.f;
#define P2(k, zn) do {                                                    \
        float z2 = (zn) * L2E;                                            \
        ez += ex2f(z2 - mz);                                              \
        ev += ex2f(sv[k][t] - mv);                                        \
        eu += ex2f(fmaf(-TAUF, z2, sP[k]) - mq);                          \
    } while (0)

#pragma unroll 4
    for (int kg = 0; kg < 16; kg++) {
        float4 zq = zp[kg];
        P2(4 * kg + 0, zq.x);
        P2(4 * kg + 1, zq.y);
        P2(4 * kg + 2, zq.z);
        P2(4 * kg + 3, zq.w);
    }
#undef P2

    float lz = mz + lg2f(ez);
    float lv = mv + lg2f(ev);
    float lu = mq + lg2f(eu);
    float tt = LN2 * fmaf(63.f, lz, fmaf(-64.f, lu, lv)) - (TAUF + 1.f) * sz;

    // block reduce tt -> g_partial
#pragma unroll
    for (int off = 16; off; off >>= 1)
        tt += __shfl_xor_sync(0xffffffffu, tt, off);
    if (lane == 0) sred[t >> 5] = tt;
    __syncthreads();
    if (t == 0) {
        float s = 0.f;
#pragma unroll
        for (int i = 0; i < ZBLK / 32; i++) s += sred[i];
        g_partial[blockIdx.x] = s;
    }

    // fused per-dim min/max of met (x already in registers)
#pragma unroll
    for (int d = 0; d < DD; d++) {
        float mn = x[d], mx = x[d];
#pragma unroll
        for (int off = 16; off; off >>= 1) {
            mn = fminf(mn, __shfl_xor_sync(0xffffffffu, mn, off));
            mx = fmaxf(mx, __shfl_xor_sync(0xffffffffu, mx, off));
        }
        if (lane == 0) {
            atomicMin(&g_minkey[d], fkey(mn));
            atomicMax(&g_maxkey[d], fkey(mx));
        }
    }
}

// ---------------- kernel 3: small losses + final sum (lgamma as literals) ----------------
__global__ void final_kernel(const float* __restrict__ mu,
                             const float* __restrict__ lambda_mu,
                             const float* __restrict__ b,
                             const float* __restrict__ Cv,
                             const float* __restrict__ rv,
                             float* __restrict__ out) {
    __shared__ float shR[DD];
    __shared__ double sred[256];
    int t = threadIdx.x;
    if (t < DD) shR[t] = fdec(g_maxkey[t]) - fdec(g_minkey[t]);
    __syncthreads();

    double R2 = 0.0;
#pragma unroll
    for (int d = 0; d < DD; d++) R2 += (double)shR[d] * (double)shR[d];
    const double cc = 5.0, gg = 4.0;                 // c = 1.25+15/4, g = 0.25+15/4
    const double Gd = cc / (50.0 * gg) * sqrt(R2);
    const double lgG = (double)__logf((float)Gd);

    // lgamma literals
    const double LG_HALF = 0.5723649429247001;       // lgamma(0.5)
    const double LG_C    = 3.1780538303479458;       // lgamma(5) = ln 24
    const double LG_G    = 1.791759469228055;        // lgamma(4) = ln 6
    const double LG_64   = 201.00931639928152;       // lgamma(64)
    const double LN_HALF = -0.6931471805599453;      // ln 0.5
    const double LN_TENTH = -2.302585092994046;      // ln 0.1

    double acc = 0.0;
    // mu quadratic + b quadratic over K*D (float math, double accumulate)
    for (int i = t; i < KK * DD; i += blockDim.x) {
        int d = i & (DD - 1);
        float lam = lambda_mu[d];
        float var = lam * lam * shR[d];
        float diff = mu[i] - b[i];
        float bb = b[i];
        acc += (double)(0.5f * diff * diff / var) + (double)(0.5f * bb * bb);
    }
    // per-dim: mu logdet + lambda prior
    for (int d = t; d < DD; d += blockDim.x) {
        float lam = lambda_mu[d];
        float var = lam * lam * shR[d];
        acc += 0.5 * (double)KK * (double)__logf(var);
        acc -= 0.5 * LN_HALF - LG_HALF - 0.5 * (double)lam - 0.5 * (double)__expf(lam);
    }
    // per-k: r prior (Gamma(c, rate=C)) + C prior (Gamma(g, rate=G))
    for (int k = t; k < KK; k += blockDim.x) {
        float rk = rv[k], Ck = Cv[k];
        acc -= cc * (double)__logf(Ck) - (cc - 1.0) * (double)rk
               - (double)Ck * (double)__expf(-rk) - LG_C;
        acc -= gg * lgG - (gg - 1.0) * (double)Ck
               - Gd * (double)__expf(-Ck) - LG_G;
    }
    // z-loss partials
    for (int i = t; i < ZGRID; i += blockDim.x) acc -= (double)g_partial[i];

    if (t == 0) {
        double sumlp = (double)g_sumlogpi;
        double G0 = LG_64 + 63.0 * LN_TENTH + sumlp;          // per-row constant in con
        acc -= (double)NN * G0;                               // z-loss constant part
        acc += (63.0 / 64.0) * sumlp;                         // pi_loss
        acc += (double)KK * 0.5 * (double)DD * DLOG2PI;       // mu_loss const
        acc += 0.5 * (double)KK * (double)DD * DLOG2PI;       // b_loss const
    }

    sred[t] = acc; __syncthreads();
    for (int s = 128; s; s >>= 1) { if (t < s) sred[t] += sred[t + s]; __syncthreads(); }
    if (t == 0) out[0] = (float)sred[0];
}

// ---------------- launch ----------------
extern "C" void kernel_launch(void* const* d_in, const int* in_sizes, int n_in,
                              void* d_out, int out_size) {
    const float* met = (const float*)d_in[0];
    const float* mu  = (const float*)d_in[1];
    const float* pi  = (const float*)d_in[2];
    const float* lam = (const float*)d_in[3];
    const float* b   = (const float*)d_in[4];
    const float* C   = (const float*)d_in[5];
    const float* r   = (const float*)d_in[6];
    const float* z   = (const float*)d_in[7];
    (void)in_sizes; (void)n_in; (void)out_size;

    prep_kernel<<<1, 64>>>(mu, pi, r);
    zloss_kernel<<<ZGRID, ZBLK>>>(met, z);
    final_kernel<<<1, 256>>>(mu, lam, b, C, r, (float*)d_out);
}

// round 5
// speedup vs baseline: 5.5567x; 1.0133x over previous
#include <cuda_runtime.h>
#include <math.h>
#include <stdint.h>

#define NN 262144
#define DD 16
#define KK 64
#define TAUF 0.1f
#define DLOG2PI 1.8378770664093454835
#define L2E 1.4426950408889634f
#define LN2 0.6931471805599453f

#define ZBLK 128
#define ZGRID (NN / ZBLK)   // 2048

// ---------------- device globals ----------------
__device__ float g_w[KK][DD];     // log2e * exp(-r_k) * mu_k[d]
__device__ float g_alpha2[KK];    // log2e * (-0.5*exp(-r_k))
__device__ float g_cc2[KK];       // log2e * (alpha*||mu_k||^2 + beta_k)
__device__ float g_logpi2[KK];    // log2e * log_softmax(pi)
__device__ float g_sumlogpi;
__device__ unsigned g_minkey[DD];
__device__ unsigned g_maxkey[DD];
__device__ float g_partial[ZGRID];

// ---------------- helpers ----------------
__device__ __forceinline__ unsigned fkey(float f) {
    unsigned u = __float_as_uint(f);
    return (u & 0x80000000u) ? ~u : (u | 0x80000000u);
}
__device__ __forceinline__ float fdec(unsigned k) {
    unsigned u = (k & 0x80000000u) ? (k & 0x7FFFFFFFu) : ~k;
    return __uint_as_float(u);
}
__device__ __forceinline__ float ex2f(float x) {
    float y; asm("ex2.approx.f32 %0, %1;" : "=f"(y) : "f"(x)); return y;
}
__device__ __forceinline__ float lg2f(float x) {
    float y; asm("lg2.approx.f32 %0, %1;" : "=f"(y) : "f"(x)); return y;
}

// ---------------- kernel 1: per-k constants + logpi + minmax init ----------------
__global__ void prep_kernel(const float* __restrict__ mu,
                            const float* __restrict__ pi,
                            const float* __restrict__ rv) {
    __shared__ float sh[KK];
    int t = threadIdx.x;          // 64 threads
    float p = pi[t];
    sh[t] = p; __syncthreads();
    for (int s = 32; s; s >>= 1) { if (t < s) sh[t] = fmaxf(sh[t], sh[t + s]); __syncthreads(); }
    float m = sh[0]; __syncthreads();
    sh[t] = __expf(p - m); __syncthreads();
    for (int s = 32; s; s >>= 1) { if (t < s) sh[t] += sh[t + s]; __syncthreads(); }
    float lse = m + __logf(sh[0]); __syncthreads();
    float lp = p - lse;
    g_logpi2[t] = lp * L2E;
    sh[t] = lp; __syncthreads();
    for (int s = 32; s; s >>= 1) { if (t < s) sh[t] += sh[t + s]; __syncthreads(); }
    if (t == 0) g_sumlogpi = sh[0];

    float rk = rv[t];
    float ie = __expf(-rk);               // 1/exp(r_k)
    float msq = 0.f;
#pragma unroll
    for (int d = 0; d < DD; d++) {
        float md = mu[t * DD + d];
        g_w[t][d] = L2E * ie * md;
        msq = fmaf(md, md, msq);
    }
    float alpha = -0.5f * ie;
    float beta  = -0.5f * 16.f * (rk + (float)DLOG2PI);
    g_alpha2[t] = L2E * alpha;
    g_cc2[t]    = L2E * fmaf(alpha, msq, beta);

    if (t < DD) { g_minkey[t] = 0xFFFFFFFFu; g_maxkey[t] = 0u; }
}

// ---------------- kernel 2: z-loss, thread-per-row, no shuffles in hot path ----------------
__global__ void __launch_bounds__(ZBLK) zloss_kernel(const float* __restrict__ met,
                                                     const float* __restrict__ z) {
    __shared__ float4 sw4[KK * 4];             // 4KB  (w rows as float4)
    __shared__ float sA[KK], sC[KK], sP[KK];   // 768B
    __shared__ float sv[KK][ZBLK];             // 32KB (v_k per thread, conflict-free)
    __shared__ float sred[ZBLK / 32];

    const int t = threadIdx.x;
    const int lane = t & 31;

    if (t < KK) { sA[t] = g_alpha2[t]; sC[t] = g_cc2[t]; sP[t] = g_logpi2[t]; }
    const float4* gw4 = reinterpret_cast<const float4*>(&g_w[0][0]);
    for (int i = t; i < KK * 4; i += ZBLK) sw4[i] = gw4[i];
    __syncthreads();

    const int row = blockIdx.x * ZBLK + t;
    const float4* xp = reinterpret_cast<const float4*>(met + (size_t)row * DD);
    float4 qa = xp[0], qb = xp[1], qc = xp[2], qd = xp[3];
    float x[DD] = { qa.x, qa.y, qa.z, qa.w, qb.x, qb.y, qb.z, qb.w,
                    qc.x, qc.y, qc.z, qc.w, qd.x, qd.y, qd.z, qd.w };
    float xs = 0.f;
#pragma unroll
    for (int d = 0; d < DD; d++) xs = fmaf(x[d], x[d], xs);

    const float4* zp = reinterpret_cast<const float4*>(z + (size_t)row * KK);

    float mz = -3.4e38f, mv = -3.4e38f, mq = -3.4e38f, sz = 0.f;

#define P1(k, zn) do {                                                    \
        const float4 wa = sw4[4*(k)+0], wb = sw4[4*(k)+1];                \
        const float4 wc = sw4[4*(k)+2], wd = sw4[4*(k)+3];                \
        float a1 = fmaf(sA[k], xs, sC[k]);                                \
        float a2 = 0.f;                                                   \
        a1 = fmaf(x[0], wa.x, a1);  a2 = fmaf(x[1], wa.y, a2);            \
        a1 = fmaf(x[2], wa.z, a1);  a2 = fmaf(x[3], wa.w, a2);            \
        a1 = fmaf(x[4], wb.x, a1);  a2 = fmaf(x[5], wb.y, a2);            \
        a1 = fmaf(x[6], wb.z, a1);  a2 = fmaf(x[7], wb.w, a2);            \
        a1 = fmaf(x[8], wc.x, a1);  a2 = fmaf(x[9], wc.y, a2);            \
        a1 = fmaf(x[10], wc.z, a1); a2 = fmaf(x[11], wc.w, a2);           \
        a1 = fmaf(x[12], wd.x, a1); a2 = fmaf(x[13], wd.y, a2);           \
        a1 = fmaf(x[14], wd.z, a1); a2 = fmaf(x[15], wd.w, a2);           \
        float z2 = (zn) * L2E;                                            \
        float v = z2 + a1 + a2;                                           \
        sv[k][t] = v;                                                     \
        mv = fmaxf(mv, v);                                                \
        mz = fmaxf(mz, z2);                                               \
        mq = fmaxf(mq, fmaf(-TAUF, z2, sP[k]));                           \
        sz += (zn);                                                       \
    } while (0)

#pragma unroll 4
    for (int kg = 0; kg < 16; kg++) {
        float4 zq = zp[kg];
        P1(4 * kg + 0, zq.x);
        P1(4 * kg + 1, zq.y);
        P1(4 * kg + 2, zq.z);
        P1(4 * kg + 3, zq.w);
    }
#undef P1

    float ez = 0.f, ev = 0.f, eu = 0.f;
#define P2(k, zn) do {                                                    \
        float z2 = (zn) * L2E;                                            \
        ez += ex2f(z2 - mz);                                              \
        ev += ex2f(sv[k][t] - mv);                                        \
        eu += ex2f(fmaf(-TAUF, z2, sP[k]) - mq);                          \
    } while (0)

#pragma unroll 4
    for (int kg = 0; kg < 16; kg++) {
        float4 zq = zp[kg];
        P2(4 * kg + 0, zq.x);
        P2(4 * kg + 1, zq.y);
        P2(4 * kg + 2, zq.z);
        P2(4 * kg + 3, zq.w);
    }
#undef P2

    float lz = mz + lg2f(ez);
    float lv = mv + lg2f(ev);
    float lu = mq + lg2f(eu);
    float tt = LN2 * fmaf(63.f, lz, fmaf(-64.f, lu, lv)) - (TAUF + 1.f) * sz;

    // block reduce tt -> g_partial
#pragma unroll
    for (int off = 16; off; off >>= 1)
        tt += __shfl_xor_sync(0xffffffffu, tt, off);
    if (lane == 0) sred[t >> 5] = tt;
    __syncthreads();
    if (t == 0) {
        float s = 0.f;
#pragma unroll
        for (int i = 0; i < ZBLK / 32; i++) s += sred[i];
        g_partial[blockIdx.x] = s;
    }

    // fused per-dim min/max of met (x already in registers)
#pragma unroll
    for (int d = 0; d < DD; d++) {
        float mn = x[d], mx = x[d];
#pragma unroll
        for (int off = 16; off; off >>= 1) {
            mn = fminf(mn, __shfl_xor_sync(0xffffffffu, mn, off));
            mx = fmaxf(mx, __shfl_xor_sync(0xffffffffu, mx, off));
        }
        if (lane == 0) {
            atomicMin(&g_minkey[d], fkey(mn));
            atomicMax(&g_maxkey[d], fkey(mx));
        }
    }
}

// ---------------- kernel 3: small losses + final sum (lgamma as literals) ----------------
__global__ void final_kernel(const float* __restrict__ mu,
                             const float* __restrict__ lambda_mu,
                             const float* __restrict__ b,
                             const float* __restrict__ Cv,
                             const float* __restrict__ rv,
                             float* __restrict__ out) {
    __shared__ float shR[DD];
    __shared__ double sred[256];
    int t = threadIdx.x;
    if (t < DD) shR[t] = fdec(g_maxkey[t]) - fdec(g_minkey[t]);
    __syncthreads();

    double R2 = 0.0;
#pragma unroll
    for (int d = 0; d < DD; d++) R2 += (double)shR[d] * (double)shR[d];
    const double cc = 5.0, gg = 4.0;                 // c = 1.25+15/4, g = 0.25+15/4
    const double Gd = cc / (50.0 * gg) * sqrt(R2);
    const double lgG = (double)__logf((float)Gd);

    // lgamma literals
    const double LG_HALF = 0.5723649429247001;       // lgamma(0.5)
    const double LG_C    = 3.1780538303479458;       // lgamma(5) = ln 24
    const double LG_G    = 1.791759469228055;        // lgamma(4) = ln 6
    const double LG_64   = 201.00931639928152;       // lgamma(64)
    const double LN_HALF = -0.6931471805599453;      // ln 0.5
    const double LN_TENTH = -2.302585092994046;      // ln 0.1

    double acc = 0.0;
    // mu quadratic + b quadratic over K*D (float math, double accumulate)
    for (int i = t; i < KK * DD; i += blockDim.x) {
        int d = i & (DD - 1);
        float lam = lambda_mu[d];
        float var = lam * lam * shR[d];
        float diff = mu[i] - b[i];
        float bb = b[i];
        acc += (double)(0.5f * diff * diff / var) + (double)(0.5f * bb * bb);
    }
    // per-dim: mu logdet + lambda prior
    for (int d = t; d < DD; d += blockDim.x) {
        float lam = lambda_mu[d];
        float var = lam * lam * shR[d];
        acc += 0.5 * (double)KK * (double)__logf(var);
        acc -= 0.5 * LN_HALF - LG_HALF - 0.5 * (double)lam - 0.5 * (double)__expf(lam);
    }
    // per-k: r prior (Gamma(c, rate=C)) + C prior (Gamma(g, rate=G))
    for (int k = t; k < KK; k += blockDim.x) {
        float rk = rv[k], Ck = Cv[k];
        acc -= cc * (double)__logf(Ck) - (cc - 1.0) * (double)rk
               - (double)Ck * (double)__expf(-rk) - LG_C;
        acc -= gg * lgG - (gg - 1.0) * (double)Ck
               - Gd * (double)__expf(-Ck) - LG_G;
    }
    // z-loss partials
    for (int i = t; i < ZGRID; i += blockDim.x) acc -= (double)g_partial[i];

    if (t == 0) {
        double sumlp = (double)g_sumlogpi;
        double G0 = LG_64 + 63.0 * LN_TENTH + sumlp;          // per-row constant in con
        acc -= (double)NN * G0;                               // z-loss constant part
        acc += (63.0 / 64.0) * sumlp;                         // pi_loss
        acc += (double)KK * 0.5 * (double)DD * DLOG2PI;       // mu_loss const
        acc += 0.5 * (double)KK * (double)DD * DLOG2PI;       // b_loss const
    }

    sred[t] = acc; __syncthreads();
    for (int s = 128; s; s >>= 1) { if (t < s) sred[t] += sred[t + s]; __syncthreads(); }
    if (t == 0) out[0] = (float)sred[0];
}

// ---------------- launch ----------------
extern "C" void kernel_launch(void* const* d_in, const int* in_sizes, int n_in,
                              void* d_out, int out_size) {
    const float* met = (const float*)d_in[0];
    const float* mu  = (const float*)d_in[1];
    const float* pi  = (const float*)d_in[2];
    const float* lam = (const float*)d_in[3];
    const float* b   = (const float*)d_in[4];
    const float* C   = (const float*)d_in[5];
    const float* r   = (const float*)d_in[6];
    const float* z   = (const float*)d_in[7];
    (void)in_sizes; (void)n_in; (void)out_size;

    prep_kernel<<<1, 64>>>(mu, pi, r);
    zloss_kernel<<<ZGRID, ZBLK>>>(met, z);
    final_kernel<<<1, 256>>>(mu, lam, b, C, r, (float*)d_out);
}

// round 6
// speedup vs baseline: 6.5770x; 1.1836x over previous
#include <cuda_runtime.h>
#include <math.h>
#include <stdint.h>

#define NN 262144
#define DD 16
#define KK 64
#define TAUF 0.1f
#define DLOG2PI 1.8378770664093454835
#define L2E 1.4426950408889634f
#define LN2 0.6931471805599453f

#define ZBLK 128
#define ZGRID (NN / ZBLK)   // 2048

// ---------------- device globals ----------------
__device__ float g_w[KK][DD];     // log2e * exp(-r_k) * mu_k[d]
__device__ float g_alpha2[KK];    // log2e * (-0.5*exp(-r_k))
__device__ float g_cc2[KK];       // log2e * (alpha*||mu_k||^2 + beta_k)
__device__ float g_logpi2[KK];    // log2e * log_softmax(pi)
__device__ float g_sumlogpi;
__device__ unsigned g_minkey[DD];
__device__ unsigned g_maxkey[DD];
__device__ float g_partial[ZGRID];

// ---------------- helpers ----------------
__device__ __forceinline__ unsigned fkey(float f) {
    unsigned u = __float_as_uint(f);
    return (u & 0x80000000u) ? ~u : (u | 0x80000000u);
}
__device__ __forceinline__ float fdec(unsigned k) {
    unsigned u = (k & 0x80000000u) ? (k & 0x7FFFFFFFu) : ~k;
    return __uint_as_float(u);
}
__device__ __forceinline__ float ex2f(float x) {
    float y; asm("ex2.approx.f32 %0, %1;" : "=f"(y) : "f"(x)); return y;
}
__device__ __forceinline__ float lg2f(float x) {
    float y; asm("lg2.approx.f32 %0, %1;" : "=f"(y) : "f"(x)); return y;
}

// ---------------- kernel 1: per-k constants + logpi + minmax init ----------------
__global__ void prep_kernel(const float* __restrict__ mu,
                            const float* __restrict__ pi,
                            const float* __restrict__ rv) {
    __shared__ float sh[KK];
    int t = threadIdx.x;          // 64 threads
    float p = pi[t];
    sh[t] = p; __syncthreads();
    for (int s = 32; s; s >>= 1) { if (t < s) sh[t] = fmaxf(sh[t], sh[t + s]); __syncthreads(); }
    float m = sh[0]; __syncthreads();
    sh[t] = __expf(p - m); __syncthreads();
    for (int s = 32; s; s >>= 1) { if (t < s) sh[t] += sh[t + s]; __syncthreads(); }
    float lse = m + __logf(sh[0]); __syncthreads();
    float lp = p - lse;
    g_logpi2[t] = lp * L2E;
    sh[t] = lp; __syncthreads();
    for (int s = 32; s; s >>= 1) { if (t < s) sh[t] += sh[t + s]; __syncthreads(); }
    if (t == 0) g_sumlogpi = sh[0];

    float rk = rv[t];
    float ie = __expf(-rk);               // 1/exp(r_k)
    float msq = 0.f;
#pragma unroll
    for (int d = 0; d < DD; d++) {
        float md = mu[t * DD + d];
        g_w[t][d] = L2E * ie * md;
        msq = fmaf(md, md, msq);
    }
    float alpha = -0.5f * ie;
    float beta  = -0.5f * 16.f * (rk + (float)DLOG2PI);
    g_alpha2[t] = L2E * alpha;
    g_cc2[t]    = L2E * fmaf(alpha, msq, beta);

    if (t < DD) { g_minkey[t] = 0xFFFFFFFFu; g_maxkey[t] = 0u; }
}

// ---------------- kernel 2: z-loss, thread-per-row ----------------
// Pass 1: dot products, v -> smem, ez/eu accumulated directly (no max needed:
//   z2 in +-10, u in [-8,-4] log2 units -> exp2 always in range).
// Pass 2: only the mix stream needs max-stabilization; 64 LDS + ex2.
__global__ void __launch_bounds__(ZBLK, 6) zloss_kernel(const float* __restrict__ met,
                                                        const float* __restrict__ z) {
    __shared__ float4 sw4[KK * 4];             // 4KB  (w rows as float4)
    __shared__ float sA[KK], sC[KK], sP[KK];   // 768B
    __shared__ float sv[KK][ZBLK];             // 32KB (v_k per thread, conflict-free)
    __shared__ float sred[ZBLK / 32];

    const int t = threadIdx.x;
    const int lane = t & 31;

    if (t < KK) { sA[t] = g_alpha2[t]; sC[t] = g_cc2[t]; sP[t] = g_logpi2[t]; }
    const float4* gw4 = reinterpret_cast<const float4*>(&g_w[0][0]);
    for (int i = t; i < KK * 4; i += ZBLK) sw4[i] = gw4[i];
    __syncthreads();

    const int row = blockIdx.x * ZBLK + t;
    const float4* xp = reinterpret_cast<const float4*>(met + (size_t)row * DD);
    float4 qa = xp[0], qb = xp[1], qc = xp[2], qd = xp[3];
    float x[DD] = { qa.x, qa.y, qa.z, qa.w, qb.x, qb.y, qb.z, qb.w,
                    qc.x, qc.y, qc.z, qc.w, qd.x, qd.y, qd.z, qd.w };
    float xs = 0.f;
#pragma unroll
    for (int d = 0; d < DD; d++) xs = fmaf(x[d], x[d], xs);

    const float4* zp = reinterpret_cast<const float4*>(z + (size_t)row * KK);

    float mv = -3.4e38f, ez = 0.f, eu = 0.f, sz = 0.f;

#define P1(k, zn) do {                                                    \
        const float4 wa = sw4[4*(k)+0], wb = sw4[4*(k)+1];                \
        const float4 wc = sw4[4*(k)+2], wd = sw4[4*(k)+3];                \
        float a1 = fmaf(sA[k], xs, sC[k]);                                \
        float a2 = 0.f;                                                   \
        a1 = fmaf(x[0], wa.x, a1);  a2 = fmaf(x[1], wa.y, a2);            \
        a1 = fmaf(x[2], wa.z, a1);  a2 = fmaf(x[3], wa.w, a2);            \
        a1 = fmaf(x[4], wb.x, a1);  a2 = fmaf(x[5], wb.y, a2);            \
        a1 = fmaf(x[6], wb.z, a1);  a2 = fmaf(x[7], wb.w, a2);            \
        a1 = fmaf(x[8], wc.x, a1);  a2 = fmaf(x[9], wc.y, a2);            \
        a1 = fmaf(x[10], wc.z, a1); a2 = fmaf(x[11], wc.w, a2);           \
        a1 = fmaf(x[12], wd.x, a1); a2 = fmaf(x[13], wd.y, a2);           \
        a1 = fmaf(x[14], wd.z, a1); a2 = fmaf(x[15], wd.w, a2);           \
        float z2 = (zn) * L2E;                                            \
        float v = z2 + a1 + a2;                                           \
        sv[k][t] = v;                                                     \
        mv = fmaxf(mv, v);                                                \
        ez += ex2f(z2);                                                   \
        eu += ex2f(fmaf(-TAUF, z2, sP[k]));                               \
        sz += (zn);                                                       \
    } while (0)

#pragma unroll 2
    for (int kg = 0; kg < 16; kg++) {
        float4 zq = zp[kg];
        P1(4 * kg + 0, zq.x);
        P1(4 * kg + 1, zq.y);
        P1(4 * kg + 2, zq.z);
        P1(4 * kg + 3, zq.w);
    }
#undef P1

    float ev = 0.f;
#pragma unroll 8
    for (int k = 0; k < KK; k++)
        ev += ex2f(sv[k][t] - mv);

    float lz = lg2f(ez);
    float lv = mv + lg2f(ev);
    float lu = lg2f(eu);
    float tt = LN2 * fmaf(63.f, lz, fmaf(-64.f, lu, lv)) - (TAUF + 1.f) * sz;

    // block reduce tt -> g_partial
#pragma unroll
    for (int off = 16; off; off >>= 1)
        tt += __shfl_xor_sync(0xffffffffu, tt, off);
    if (lane == 0) sred[t >> 5] = tt;
    __syncthreads();
    if (t == 0) {
        float s = 0.f;
#pragma unroll
        for (int i = 0; i < ZBLK / 32; i++) s += sred[i];
        g_partial[blockIdx.x] = s;
    }

    // fused per-dim min/max of met (x already in registers)
#pragma unroll
    for (int d = 0; d < DD; d++) {
        float mn = x[d], mx = x[d];
#pragma unroll
        for (int off = 16; off; off >>= 1) {
            mn = fminf(mn, __shfl_xor_sync(0xffffffffu, mn, off));
            mx = fmaxf(mx, __shfl_xor_sync(0xffffffffu, mx, off));
        }
        if (lane == 0) {
            atomicMin(&g_minkey[d], fkey(mn));
            atomicMax(&g_maxkey[d], fkey(mx));
        }
    }
}

// ---------------- kernel 3: small losses + final sum (lgamma as literals) ----------------
__global__ void final_kernel(const float* __restrict__ mu,
                             const float* __restrict__ lambda_mu,
                             const float* __restrict__ b,
                             const float* __restrict__ Cv,
                             const float* __restrict__ rv,
                             float* __restrict__ out) {
    __shared__ float shR[DD];
    __shared__ double sred[256];
    int t = threadIdx.x;
    if (t < DD) shR[t] = fdec(g_maxkey[t]) - fdec(g_minkey[t]);
    __syncthreads();

    double R2 = 0.0;
#pragma unroll
    for (int d = 0; d < DD; d++) R2 += (double)shR[d] * (double)shR[d];
    const double cc = 5.0, gg = 4.0;                 // c = 1.25+15/4, g = 0.25+15/4
    const double Gd = cc / (50.0 * gg) * sqrt(R2);
    const double lgG = (double)__logf((float)Gd);

    // lgamma literals
    const double LG_HALF = 0.5723649429247001;       // lgamma(0.5)
    const double LG_C    = 3.1780538303479458;       // lgamma(5) = ln 24
    const double LG_G    = 1.791759469228055;        // lgamma(4) = ln 6
    const double LG_64   = 201.00931639928152;       // lgamma(64)
    const double LN_HALF = -0.6931471805599453;      // ln 0.5
    const double LN_TENTH = -2.302585092994046;      // ln 0.1

    double acc = 0.0;
    // mu quadratic + b quadratic over K*D (float math, double accumulate)
    for (int i = t; i < KK * DD; i += blockDim.x) {
        int d = i & (DD - 1);
        float lam = lambda_mu[d];
        float var = lam * lam * shR[d];
        float diff = mu[i] - b[i];
        float bb = b[i];
        acc += (double)(0.5f * diff * diff / var) + (double)(0.5f * bb * bb);
    }
    // per-dim: mu logdet + lambda prior
    for (int d = t; d < DD; d += blockDim.x) {
        float lam = lambda_mu[d];
        float var = lam * lam * shR[d];
        acc += 0.5 * (double)KK * (double)__logf(var);
        acc -= 0.5 * LN_HALF - LG_HALF - 0.5 * (double)lam - 0.5 * (double)__expf(lam);
    }
    // per-k: r prior (Gamma(c, rate=C)) + C prior (Gamma(g, rate=G))
    for (int k = t; k < KK; k += blockDim.x) {
        float rk = rv[k], Ck = Cv[k];
        acc -= cc * (double)__logf(Ck) - (cc - 1.0) * (double)rk
               - (double)Ck * (double)__expf(-rk) - LG_C;
        acc -= gg * lgG - (gg - 1.0) * (double)Ck
               - Gd * (double)__expf(-Ck) - LG_G;
    }
    // z-loss partials
    for (int i = t; i < ZGRID; i += blockDim.x) acc -= (double)g_partial[i];

    if (t == 0) {
        double sumlp = (double)g_sumlogpi;
        double G0 = LG_64 + 63.0 * LN_TENTH + sumlp;          // per-row constant in con
        acc -= (double)NN * G0;                               // z-loss constant part
        acc += (63.0 / 64.0) * sumlp;                         // pi_loss
        acc += (double)KK * 0.5 * (double)DD * DLOG2PI;       // mu_loss const
        acc += 0.5 * (double)KK * (double)DD * DLOG2PI;       // b_loss const
    }

    sred[t] = acc; __syncthreads();
    for (int s = 128; s; s >>= 1) { if (t < s) sred[t] += sred[t + s]; __syncthreads(); }
    if (t == 0) out[0] = (float)sred[0];
}

// ---------------- launch ----------------
extern "C" void kernel_launch(void* const* d_in, const int* in_sizes, int n_in,
                              void* d_out, int out_size) {
    const float* met = (const float*)d_in[0];
    const float* mu  = (const float*)d_in[1];
    const float* pi  = (const float*)d_in[2];
    const float* lam = (const float*)d_in[3];
    const float* b   = (const float*)d_in[4];
    const float* C   = (const float*)d_in[5];
    const float* r   = (const float*)d_in[6];
    const float* z   = (const float*)d_in[7];
    (void)in_sizes; (void)n_in; (void)out_size;

    prep_kernel<<<1, 64>>>(mu, pi, r);
    zloss_kernel<<<ZGRID, ZBLK>>>(met, z);
    final_kernel<<<1, 256>>>(mu, lam, b, C, r, (float*)d_out);
}

// round 7
// speedup vs baseline: 6.9793x; 1.0612x over previous
#include <cuda_runtime.h>
#include <math.h>
#include <stdint.h>

#define NN 262144
#define DD 16
#define KK 64
#define TAUF 0.1f
#define DLOG2PI 1.8378770664093454835
#define L2E 1.4426950408889634f
#define LN2 0.6931471805599453f

#define ZBLK 128
#define ZGRID (NN / ZBLK)   // 2048

// ---------------- device globals ----------------
__device__ float g_sumlogpi;
__device__ unsigned g_minkey[DD] = {
    0xFFFFFFFFu,0xFFFFFFFFu,0xFFFFFFFFu,0xFFFFFFFFu,0xFFFFFFFFu,0xFFFFFFFFu,0xFFFFFFFFu,0xFFFFFFFFu,
    0xFFFFFFFFu,0xFFFFFFFFu,0xFFFFFFFFu,0xFFFFFFFFu,0xFFFFFFFFu,0xFFFFFFFFu,0xFFFFFFFFu,0xFFFFFFFFu};
__device__ unsigned g_maxkey[DD] = {0,0,0,0,0,0,0,0,0,0,0,0,0,0,0,0};
__device__ float g_partial[ZGRID];

// ---------------- helpers ----------------
__device__ __forceinline__ unsigned fkey(float f) {
    unsigned u = __float_as_uint(f);
    return (u & 0x80000000u) ? ~u : (u | 0x80000000u);
}
__device__ __forceinline__ float fdec(unsigned k) {
    unsigned u = (k & 0x80000000u) ? (k & 0x7FFFFFFFu) : ~k;
    return __uint_as_float(u);
}
__device__ __forceinline__ float ex2f(float x) {
    float y; asm("ex2.approx.f32 %0, %1;" : "=f"(y) : "f"(x)); return y;
}
__device__ __forceinline__ float lg2f(float x) {
    float y; asm("lg2.approx.f32 %0, %1;" : "=f"(y) : "f"(x)); return y;
}
__device__ __forceinline__ unsigned long long pk2(float lo, float hi) {
    unsigned long long r;
    asm("mov.b64 %0, {%1, %2};" : "=l"(r) : "f"(lo), "f"(hi));
    return r;
}
#define FMA2(d, a, b, c) \
    asm("fma.rn.f32x2 %0, %1, %2, %3;" : "=l"(d) : "l"(a), "l"(b), "l"(c))
#define ADD2(d, a, b) \
    asm("add.rn.f32x2 %0, %1, %2;" : "=l"(d) : "l"(a), "l"(b))
__device__ __forceinline__ void upk2(unsigned long long v, float& lo, float& hi) {
    asm("mov.b64 {%0, %1}, %2;" : "=f"(lo), "=f"(hi) : "l"(v));
}

// ---------------- kernel 1: z-loss (prep fused, staged z, online lse) ----------------
__global__ void __launch_bounds__(ZBLK, 6) zloss_kernel(const float* __restrict__ met,
                                                        const float* __restrict__ z,
                                                        const float* __restrict__ mu,
                                                        const float* __restrict__ pi,
                                                        const float* __restrict__ rv) {
    __shared__ float4 swq[KK * 5];      // per k: w[0..15] (4xf4) + (A, C, lp2, 0)
    __shared__ float SZ[ZBLK * KK];     // 32KB staged z, rotated float4 layout
    __shared__ float spi[KK];
    __shared__ float slse;
    __shared__ float sred[ZBLK / 32];

    const int t = threadIdx.x;
    const int lane = t & 31;

    // ---- prep: softmax(pi) ----
    if (t < KK) spi[t] = pi[t];
    __syncthreads();
    if (t < 32) {
        float a = spi[t], b2 = spi[t + 32];
        float m = fmaxf(a, b2);
#pragma unroll
        for (int off = 16; off; off >>= 1)
            m = fmaxf(m, __shfl_xor_sync(0xffffffffu, m, off));
        float es = __expf(a - m) + __expf(b2 - m);
        float sp = a + b2;
#pragma unroll
        for (int off = 16; off; off >>= 1) {
            es += __shfl_xor_sync(0xffffffffu, es, off);
            sp += __shfl_xor_sync(0xffffffffu, sp, off);
        }
        float lse = m + __logf(es);
        if (t == 0) {
            slse = lse;
            if (blockIdx.x == 0) g_sumlogpi = sp - 64.f * lse;
        }
    }
    __syncthreads();

    // ---- prep: per-k constants into swq ----
    if (t < KK) {
        float lp2 = (spi[t] - slse) * L2E;
        float rk = rv[t];
        float ie = __expf(-rk);
        float sc = L2E * ie;
        const float4* mu4 = reinterpret_cast<const float4*>(mu + t * DD);
        float msq = 0.f;
#pragma unroll
        for (int q = 0; q < 4; q++) {
            float4 mq = mu4[q];
            msq = fmaf(mq.x, mq.x, msq); msq = fmaf(mq.y, mq.y, msq);
            msq = fmaf(mq.z, mq.z, msq); msq = fmaf(mq.w, mq.w, msq);
            swq[t * 5 + q] = make_float4(sc * mq.x, sc * mq.y, sc * mq.z, sc * mq.w);
        }
        float alpha = -0.5f * ie;
        float beta  = -0.5f * 16.f * (rk + (float)DLOG2PI);
        swq[t * 5 + 4] = make_float4(L2E * alpha, L2E * fmaf(alpha, msq, beta), lp2, 0.f);
    }

    // ---- stage z coalesced into smem (rotated float4 layout) ----
    const float4* zg = reinterpret_cast<const float4*>(z) + (size_t)blockIdx.x * (ZBLK * KK / 4);
#pragma unroll
    for (int j = 0; j < 16; j++) {
        int fl = j * ZBLK + t;
        float4 v = zg[fl];
        int r = fl >> 4;            // local row
        int c = fl & 15;            // float4 col
        *reinterpret_cast<float4*>(&SZ[r * 64 + (((c + r) & 15) << 2)]) = v;
    }

    // ---- load met row ----
    const int row = blockIdx.x * ZBLK + t;
    const float4* xp = reinterpret_cast<const float4*>(met + (size_t)row * DD);
    float4 qa = xp[0], qb = xp[1], qc = xp[2], qd = xp[3];
    float x[DD] = { qa.x, qa.y, qa.z, qa.w, qb.x, qb.y, qb.z, qb.w,
                    qc.x, qc.y, qc.z, qc.w, qd.x, qd.y, qd.z, qd.w };
    float xs = 0.f;
#pragma unroll
    for (int d = 0; d < DD; d++) xs = fmaf(x[d], x[d], xs);
    unsigned long long x2[8];
#pragma unroll
    for (int i = 0; i < 8; i++) x2[i] = pk2(x[2 * i], x[2 * i + 1]);

    __syncthreads();

    // ---- main k loop ----
    const int t64 = t * 64;
    const int tr = t & 15;
    float mv = -3.0e38f, ev = 0.f, ez = 0.f, eu = 0.f, szs = 0.f;

#pragma unroll 8
    for (int k = 0; k < KK; k++) {
        const ulonglong2* wp = reinterpret_cast<const ulonglong2*>(&swq[k * 5]);
        ulonglong2 q0 = wp[0], q1 = wp[1];
        float4 acp = swq[k * 5 + 4];

        unsigned long long A0 = 0ull, A1 = 0ull;
        FMA2(A0, x2[0], q0.x, A0); FMA2(A1, x2[1], q0.y, A1);
        FMA2(A0, x2[2], q1.x, A0); FMA2(A1, x2[3], q1.y, A1);
        ulonglong2 q2 = wp[2], q3 = wp[3];
        FMA2(A0, x2[4], q2.x, A0); FMA2(A1, x2[5], q2.y, A1);
        FMA2(A0, x2[6], q3.x, A0); FMA2(A1, x2[7], q3.y, A1);
        ADD2(A0, A0, A1);
        float dlo, dhi; upk2(A0, dlo, dhi);
        float logN = dlo + dhi + fmaf(acp.x, xs, acp.y);   // log2-units

        float zn = SZ[t64 + ((((k >> 2) + tr) & 15) << 2) + (k & 3)];
        float z2 = zn * L2E;
        szs += zn;
        ez += ex2f(z2);
        eu += ex2f(fmaf(-TAUF, z2, acp.z));

        float vv = z2 + logN;
        float mvn = fmaxf(mv, vv);
        ev = ev * ex2f(mv - mvn) + ex2f(vv - mvn);
        mv = mvn;
    }

    float lz = lg2f(ez);
    float lv = mv + lg2f(ev);
    float lu = lg2f(eu);
    float tt = LN2 * fmaf(63.f, lz, fmaf(-64.f, lu, lv)) - (TAUF + 1.f) * szs;

    // block reduce tt -> g_partial
#pragma unroll
    for (int off = 16; off; off >>= 1)
        tt += __shfl_xor_sync(0xffffffffu, tt, off);
    if (lane == 0) sred[t >> 5] = tt;
    __syncthreads();
    if (t == 0) {
        float s = 0.f;
#pragma unroll
        for (int i = 0; i < ZBLK / 32; i++) s += sred[i];
        g_partial[blockIdx.x] = s;
    }

    // fused per-dim min/max of met (x already in registers)
#pragma unroll
    for (int d = 0; d < DD; d++) {
        float mn = x[d], mx = x[d];
#pragma unroll
        for (int off = 16; off; off >>= 1) {
            mn = fminf(mn, __shfl_xor_sync(0xffffffffu, mn, off));
            mx = fmaxf(mx, __shfl_xor_sync(0xffffffffu, mx, off));
        }
        if (lane == 0) {
            atomicMin(&g_minkey[d], fkey(mn));
            atomicMax(&g_maxkey[d], fkey(mx));
        }
    }
}

// ---------------- kernel 2: small losses + final sum (lgamma as literals) ----------------
__global__ void final_kernel(const float* __restrict__ mu,
                             const float* __restrict__ lambda_mu,
                             const float* __restrict__ b,
                             const float* __restrict__ Cv,
                             const float* __restrict__ rv,
                             float* __restrict__ out) {
    __shared__ float shR[DD];
    __shared__ double sred[256];
    int t = threadIdx.x;
    if (t < DD) shR[t] = fdec(g_maxkey[t]) - fdec(g_minkey[t]);
    __syncthreads();

    double R2 = 0.0;
#pragma unroll
    for (int d = 0; d < DD; d++) R2 += (double)shR[d] * (double)shR[d];
    const double cc = 5.0, gg = 4.0;                 // c = 1.25+15/4, g = 0.25+15/4
    const double Gd = cc / (50.0 * gg) * sqrt(R2);
    const double lgG = (double)__logf((float)Gd);

    // lgamma literals
    const double LG_HALF = 0.5723649429247001;       // lgamma(0.5)
    const double LG_C    = 3.1780538303479458;       // lgamma(5) = ln 24
    const double LG_G    = 1.791759469228055;        // lgamma(4) = ln 6
    const double LG_64   = 201.00931639928152;       // lgamma(64)
    const double LN_HALF = -0.6931471805599453;      // ln 0.5
    const double LN_TENTH = -2.302585092994046;      // ln 0.1

    double acc = 0.0;
    for (int i = t; i < KK * DD; i += blockDim.x) {
        int d = i & (DD - 1);
        float lam = lambda_mu[d];
        float var = lam * lam * shR[d];
        float diff = mu[i] - b[i];
        float bb = b[i];
        acc += (double)(0.5f * diff * diff / var) + (double)(0.5f * bb * bb);
    }
    for (int d = t; d < DD; d += blockDim.x) {
        float lam = lambda_mu[d];
        float var = lam * lam * shR[d];
        acc += 0.5 * (double)KK * (double)__logf(var);
        acc -= 0.5 * LN_HALF - LG_HALF - 0.5 * (double)lam - 0.5 * (double)__expf(lam);
    }
    for (int k = t; k < KK; k += blockDim.x) {
        float rk = rv[k], Ck = Cv[k];
        acc -= cc * (double)__logf(Ck) - (cc - 1.0) * (double)rk
               - (double)Ck * (double)__expf(-rk) - LG_C;
        acc -= gg * lgG - (gg - 1.0) * (double)Ck
               - Gd * (double)__expf(-Ck) - LG_G;
    }
    for (int i = t; i < ZGRID; i += blockDim.x) acc -= (double)g_partial[i];

    if (t == 0) {
        double sumlp = (double)g_sumlogpi;
        double G0 = LG_64 + 63.0 * LN_TENTH + sumlp;          // per-row constant in con
        acc -= (double)NN * G0;                               // z-loss constant part
        acc += (63.0 / 64.0) * sumlp;                         // pi_loss
        acc += (double)KK * 0.5 * (double)DD * DLOG2PI;       // mu_loss const
        acc += 0.5 * (double)KK * (double)DD * DLOG2PI;       // b_loss const
    }

    sred[t] = acc; __syncthreads();
    for (int s = 128; s; s >>= 1) { if (t < s) sred[t] += sred[t + s]; __syncthreads(); }
    if (t == 0) out[0] = (float)sred[0];
}

// ---------------- launch ----------------
extern "C" void kernel_launch(void* const* d_in, const int* in_sizes, int n_in,
                              void* d_out, int out_size) {
    const float* met = (const float*)d_in[0];
    const float* mu  = (const float*)d_in[1];
    const float* pi  = (const float*)d_in[2];
    const float* lam = (const float*)d_in[3];
    const float* b   = (const float*)d_in[4];
    const float* C   = (const float*)d_in[5];
    const float* r   = (const float*)d_in[6];
    const float* z   = (const float*)d_in[7];
    (void)in_sizes; (void)n_in; (void)out_size;

    zloss_kernel<<<ZGRID, ZBLK>>>(met, z, mu, pi, r);
    final_kernel<<<1, 256>>>(mu, lam, b, C, r, (float*)d_out);
}

// round 8
// speedup vs baseline: 15.0912x; 2.1623x over previous
#include <cuda_runtime.h>
#include <math.h>
#include <stdint.h>

#define NN 262144
#define DD 16
#define KK 64
#define TAUF 0.1f
#define DLOG2PI 1.8378770664093454835
#define L2E 1.4426950408889634f
#define LN2 0.6931471805599453f

#define ZBLK 128
#define ZGRID (NN / ZBLK)   // 2048

// ---------------- device globals ----------------
__device__ float g_sumlogpi;
__device__ unsigned g_minkey[DD] = {
    0xFFFFFFFFu,0xFFFFFFFFu,0xFFFFFFFFu,0xFFFFFFFFu,0xFFFFFFFFu,0xFFFFFFFFu,0xFFFFFFFFu,0xFFFFFFFFu,
    0xFFFFFFFFu,0xFFFFFFFFu,0xFFFFFFFFu,0xFFFFFFFFu,0xFFFFFFFFu,0xFFFFFFFFu,0xFFFFFFFFu,0xFFFFFFFFu};
__device__ unsigned g_maxkey[DD] = {0,0,0,0,0,0,0,0,0,0,0,0,0,0,0,0};
__device__ float g_partial[ZGRID];
__device__ unsigned g_ctr = 0;

// ---------------- helpers ----------------
__device__ __forceinline__ unsigned fkey(float f) {
    unsigned u = __float_as_uint(f);
    return (u & 0x80000000u) ? ~u : (u | 0x80000000u);
}
__device__ __forceinline__ float fdec(unsigned k) {
    unsigned u = (k & 0x80000000u) ? (k & 0x7FFFFFFFu) : ~k;
    return __uint_as_float(u);
}
__device__ __forceinline__ float ex2f(float x) {
    float y; asm("ex2.approx.f32 %0, %1;" : "=f"(y) : "f"(x)); return y;
}
__device__ __forceinline__ float lg2f(float x) {
    float y; asm("lg2.approx.f32 %0, %1;" : "=f"(y) : "f"(x)); return y;
}
__device__ __forceinline__ unsigned long long pk2(float lo, float hi) {
    unsigned long long r;
    asm("mov.b64 %0, {%1, %2};" : "=l"(r) : "f"(lo), "f"(hi));
    return r;
}
#define FMA2(d, a, b, c) \
    asm("fma.rn.f32x2 %0, %1, %2, %3;" : "=l"(d) : "l"(a), "l"(b), "l"(c))
#define ADD2(d, a, b) \
    asm("add.rn.f32x2 %0, %1, %2;" : "=l"(d) : "l"(a), "l"(b))
__device__ __forceinline__ void upk2(unsigned long long v, float& lo, float& hi) {
    asm("mov.b64 {%0, %1}, %2;" : "=f"(lo), "=f"(hi) : "l"(v));
}

// ---------------- single fused kernel ----------------
__global__ void __launch_bounds__(ZBLK, 6) zloss_kernel(const float* __restrict__ met,
                                                        const float* __restrict__ z,
                                                        const float* __restrict__ mu,
                                                        const float* __restrict__ pi,
                                                        const float* __restrict__ rv,
                                                        const float* __restrict__ lambda_mu,
                                                        const float* __restrict__ bv,
                                                        const float* __restrict__ Cv,
                                                        float* __restrict__ out) {
    __shared__ float4 swq[KK * 5];      // per k: w[0..15] (4xf4) + (A, C, lp2, 0)   5 KB
    __shared__ float SZ[ZBLK * 33];     // staged half-z, stride 33 (bank-conflict-free) 16.9 KB
    __shared__ float spi[KK];
    __shared__ float slse;
    __shared__ float sred[4];
    __shared__ float smn[4][DD], smx[4][DD];
    __shared__ unsigned s_last;

    const int t = threadIdx.x;
    const int lane = t & 31;
    const int wid = t >> 5;

    // ---- prep: softmax(pi) ----
    if (t < KK) spi[t] = pi[t];
    __syncthreads();
    if (t < 32) {
        float a = spi[t], b2 = spi[t + 32];
        float m = fmaxf(a, b2);
#pragma unroll
        for (int off = 16; off; off >>= 1)
            m = fmaxf(m, __shfl_xor_sync(0xffffffffu, m, off));
        float es = __expf(a - m) + __expf(b2 - m);
        float sp = a + b2;
#pragma unroll
        for (int off = 16; off; off >>= 1) {
            es += __shfl_xor_sync(0xffffffffu, es, off);
            sp += __shfl_xor_sync(0xffffffffu, sp, off);
        }
        float lse = m + __logf(es);
        if (t == 0) {
            slse = lse;
            if (blockIdx.x == 0) g_sumlogpi = sp - 64.f * lse;
        }
    }
    __syncthreads();

    // ---- prep: per-k constants into swq ----
    if (t < KK) {
        float lp2 = (spi[t] - slse) * L2E;
        float rk = rv[t];
        float ie = __expf(-rk);
        float sc = L2E * ie;
        const float4* mu4 = reinterpret_cast<const float4*>(mu + t * DD);
        float msq = 0.f;
#pragma unroll
        for (int q = 0; q < 4; q++) {
            float4 mq = mu4[q];
            msq = fmaf(mq.x, mq.x, msq); msq = fmaf(mq.y, mq.y, msq);
            msq = fmaf(mq.z, mq.z, msq); msq = fmaf(mq.w, mq.w, msq);
            swq[t * 5 + q] = make_float4(sc * mq.x, sc * mq.y, sc * mq.z, sc * mq.w);
        }
        float alpha = -0.5f * ie;
        float beta  = -0.5f * 16.f * (rk + (float)DLOG2PI);
        swq[t * 5 + 4] = make_float4(L2E * alpha, L2E * fmaf(alpha, msq, beta), lp2, 0.f);
    }

    // ---- load met row, pack x2, xs ----
    const int row = blockIdx.x * ZBLK + t;
    const float4* xp = reinterpret_cast<const float4*>(met + (size_t)row * DD);
    float4 qa = xp[0], qb = xp[1], qc = xp[2], qd = xp[3];
    float xs = 0.f;
    xs = fmaf(qa.x, qa.x, xs); xs = fmaf(qa.y, qa.y, xs); xs = fmaf(qa.z, qa.z, xs); xs = fmaf(qa.w, qa.w, xs);
    xs = fmaf(qb.x, qb.x, xs); xs = fmaf(qb.y, qb.y, xs); xs = fmaf(qb.z, qb.z, xs); xs = fmaf(qb.w, qb.w, xs);
    xs = fmaf(qc.x, qc.x, xs); xs = fmaf(qc.y, qc.y, xs); xs = fmaf(qc.z, qc.z, xs); xs = fmaf(qc.w, qc.w, xs);
    xs = fmaf(qd.x, qd.x, xs); xs = fmaf(qd.y, qd.y, xs); xs = fmaf(qd.z, qd.z, xs); xs = fmaf(qd.w, qd.w, xs);
    unsigned long long x2[8];
    x2[0] = pk2(qa.x, qa.y); x2[1] = pk2(qa.z, qa.w);
    x2[2] = pk2(qb.x, qb.y); x2[3] = pk2(qb.z, qb.w);
    x2[4] = pk2(qc.x, qc.y); x2[5] = pk2(qc.z, qc.w);
    x2[6] = pk2(qd.x, qd.y); x2[7] = pk2(qd.z, qd.w);

    // ---- two-phase staged main loop ----
    const float4* zg = reinterpret_cast<const float4*>(z) + (size_t)blockIdx.x * (ZBLK * KK / 4);
    float mv = -3.0e38f, ev = 0.f, ez = 0.f, eu = 0.f, sz2 = 0.f;

#pragma unroll 1
    for (int half = 0; half < 2; half++) {
        if (half) __syncthreads();                 // readers of previous half done
        // stage 32 z-columns, pre-scaled by log2e; stride-33 conflict-free layout
#pragma unroll
        for (int j = 0; j < 8; j++) {
            int idx = j * ZBLK + t;
            int r = idx >> 3, c = idx & 7;
            float4 v = zg[r * 16 + half * 8 + c];
            float* sp2 = &SZ[r * 33 + c * 4];
            sp2[0] = v.x * L2E; sp2[1] = v.y * L2E; sp2[2] = v.z * L2E; sp2[3] = v.w * L2E;
        }
        __syncthreads();

        const int kb = half * 32;
#pragma unroll 1
        for (int cch = 0; cch < 4; cch++) {
            float vv[8];
#pragma unroll
            for (int i = 0; i < 8; i++) {
                const int kk = cch * 8 + i;
                const int k = kb + kk;
                const ulonglong2* wp = reinterpret_cast<const ulonglong2*>(&swq[k * 5]);
                float4 acp = swq[k * 5 + 4];
                float z2 = SZ[t * 33 + kk];
                unsigned long long A0 = pk2(fmaf(acp.x, xs, acp.y), z2);
                unsigned long long A1 = 0ull;
                ulonglong2 q0 = wp[0], q1 = wp[1], q2 = wp[2], q3 = wp[3];
                FMA2(A0, x2[0], q0.x, A0); FMA2(A1, x2[1], q0.y, A1);
                FMA2(A0, x2[2], q1.x, A0); FMA2(A1, x2[3], q1.y, A1);
                FMA2(A0, x2[4], q2.x, A0); FMA2(A1, x2[5], q2.y, A1);
                FMA2(A0, x2[6], q3.x, A0); FMA2(A1, x2[7], q3.y, A1);
                ADD2(A0, A0, A1);
                float dlo, dhi; upk2(A0, dlo, dhi);
                vv[i] = dlo + dhi;                 // z2 + logN (log2 units)
                ez += ex2f(z2);
                eu += ex2f(fmaf(-TAUF, z2, acp.z));
                sz2 += z2;
            }
            float m8 = fmaxf(fmaxf(fmaxf(vv[0], vv[1]), fmaxf(vv[2], vv[3])),
                             fmaxf(fmaxf(vv[4], vv[5]), fmaxf(vv[6], vv[7])));
            float mvn = fmaxf(mv, m8);
            float s8 = ex2f(vv[0] - mvn) + ex2f(vv[1] - mvn)
                     + ex2f(vv[2] - mvn) + ex2f(vv[3] - mvn)
                     + ex2f(vv[4] - mvn) + ex2f(vv[5] - mvn)
                     + ex2f(vv[6] - mvn) + ex2f(vv[7] - mvn);
            ev = fmaf(ev, ex2f(mv - mvn), s8);
            mv = mvn;
        }
    }

    float lz = lg2f(ez);
    float lv = mv + lg2f(ev);
    float lu = lg2f(eu);
    float tt = LN2 * (fmaf(63.f, lz, fmaf(-64.f, lu, lv)) - (TAUF + 1.f) * sz2);

    // ---- per-dim min/max: warp reduce -> block reduce -> 32 atomics/block ----
#pragma unroll
    for (int i = 0; i < 8; i++) {
        float lo, hi; upk2(x2[i], lo, hi);
        float mn0 = lo, mx0 = lo, mn1 = hi, mx1 = hi;
#pragma unroll
        for (int off = 16; off; off >>= 1) {
            mn0 = fminf(mn0, __shfl_xor_sync(0xffffffffu, mn0, off));
            mx0 = fmaxf(mx0, __shfl_xor_sync(0xffffffffu, mx0, off));
            mn1 = fminf(mn1, __shfl_xor_sync(0xffffffffu, mn1, off));
            mx1 = fmaxf(mx1, __shfl_xor_sync(0xffffffffu, mx1, off));
        }
        if (lane == 0) {
            smn[wid][2 * i] = mn0;     smx[wid][2 * i] = mx0;
            smn[wid][2 * i + 1] = mn1; smx[wid][2 * i + 1] = mx1;
        }
    }

    // ---- block reduce tt ----
#pragma unroll
    for (int off = 16; off; off >>= 1)
        tt += __shfl_xor_sync(0xffffffffu, tt, off);
    if (lane == 0) sred[wid] = tt;
    __syncthreads();

    if (t < DD) {
        float mn = fminf(fminf(smn[0][t], smn[1][t]), fminf(smn[2][t], smn[3][t]));
        atomicMin(&g_minkey[t], fkey(mn));
    } else if (t < 2 * DD) {
        int d = t - DD;
        float mx = fmaxf(fmaxf(smx[0][d], smx[1][d]), fmaxf(smx[2][d], smx[3][d]));
        atomicMax(&g_maxkey[d], fkey(mx));
    }
    __syncthreads();                       // minmax atomics + partial issued before signal

    if (t == 0) {
        g_partial[blockIdx.x] = sred[0] + sred[1] + sred[2] + sred[3];
        __threadfence();
        unsigned old = atomicAdd(&g_ctr, 1u);
        s_last = (old == (unsigned)(ZGRID - 1)) ? 1u : 0u;
    }
    __syncthreads();
    if (!s_last) return;

    // ================= last block: final scalar epilogue =================
    __threadfence();
    float* shR = spi;                      // reuse
    if (t < DD) shR[t] = fdec(g_maxkey[t]) - fdec(g_minkey[t]);
    __syncthreads();

    double R2 = 0.0;
#pragma unroll
    for (int d = 0; d < DD; d++) R2 += (double)shR[d] * (double)shR[d];
    const double cc = 5.0, gg = 4.0;
    const double Gd = cc / (50.0 * gg) * sqrt(R2);
    const double lgG = (double)__logf((float)Gd);

    const double LG_HALF = 0.5723649429247001;       // lgamma(0.5)
    const double LG_C    = 3.1780538303479458;       // lgamma(5)
    const double LG_G    = 1.791759469228055;        // lgamma(4)
    const double LG_64   = 201.00931639928152;       // lgamma(64)
    const double LN_HALF = -0.6931471805599453;
    const double LN_TENTH = -2.302585092994046;

    double acc = 0.0;
    for (int i = t; i < KK * DD; i += ZBLK) {
        int d = i & (DD - 1);
        float lam = lambda_mu[d];
        float var = lam * lam * shR[d];
        float diff = mu[i] - bv[i];
        float bb = bv[i];
        acc += (double)(0.5f * diff * diff / var) + (double)(0.5f * bb * bb);
    }
    for (int d = t; d < DD; d += ZBLK) {
        float lam = lambda_mu[d];
        float var = lam * lam * shR[d];
        acc += 0.5 * (double)KK * (double)__logf(var);
        acc -= 0.5 * LN_HALF - LG_HALF - 0.5 * (double)lam - 0.5 * (double)__expf(lam);
    }
    for (int k = t; k < KK; k += ZBLK) {
        float rk = rv[k], Ck = Cv[k];
        acc -= cc * (double)__logf(Ck) - (cc - 1.0) * (double)rk
               - (double)Ck * (double)__expf(-rk) - LG_C;
        acc -= gg * lgG - (gg - 1.0) * (double)Ck
               - Gd * (double)__expf(-Ck) - LG_G;
    }
    const float4* p4 = reinterpret_cast<const float4*>(g_partial);
    for (int i = t; i < ZGRID / 4; i += ZBLK) {
        float4 v = p4[i];
        acc -= (double)v.x + (double)v.y + (double)v.z + (double)v.w;
    }

    double* dred = reinterpret_cast<double*>(SZ);    // overlay (SZ no longer needed)
    dred[t] = acc;
    __syncthreads();
#pragma unroll
    for (int s = 64; s; s >>= 1) {
        if (t < s) dred[t] += dred[t + s];
        __syncthreads();
    }
    if (t == 0) {
        double total = dred[0];
        double sumlp = (double)g_sumlogpi;
        double G0 = LG_64 + 63.0 * LN_TENTH + sumlp;          // per-row constant in con
        total -= (double)NN * G0;                             // z-loss constant part
        total += (63.0 / 64.0) * sumlp;                       // pi_loss
        total += (double)KK * 0.5 * (double)DD * DLOG2PI;     // mu_loss const
        total += 0.5 * (double)KK * (double)DD * DLOG2PI;     // b_loss const
        out[0] = (float)total;
        atomicExch(&g_ctr, 0u);                               // reset for graph replay
    }
}

// ---------------- launch ----------------
extern "C" void kernel_launch(void* const* d_in, const int* in_sizes, int n_in,
                              void* d_out, int out_size) {
    const float* met = (const float*)d_in[0];
    const float* mu  = (const float*)d_in[1];
    const float* pi  = (const float*)d_in[2];
    const float* lam = (const float*)d_in[3];
    const float* b   = (const float*)d_in[4];
    const float* C   = (const float*)d_in[5];
    const float* r   = (const float*)d_in[6];
    const float* z   = (const float*)d_in[7];
    (void)in_sizes; (void)n_in; (void)out_size;

    zloss_kernel<<<ZGRID, ZBLK>>>(met, z, mu, pi, r, lam, b, C, (float*)d_out);
}

// round 9
// speedup vs baseline: 17.2215x; 1.1412x over previous
#include <cuda_runtime.h>
#include <math.h>
#include <stdint.h>

#define NN 262144
#define DD 16
#define KK 64
#define TAUF 0.1f
#define DLOG2PI 1.8378770664093454835
#define L2E 1.4426950408889634f
#define LN2 0.6931471805599453f

#define TPB 128            // threads per block
#define RPB 256            // rows per block (2 rows per thread)
#define ZGRID (NN / RPB)   // 1024

// ---------------- device globals ----------------
__device__ float g_sumlogpi;
__device__ unsigned g_minkey[DD] = {
    0xFFFFFFFFu,0xFFFFFFFFu,0xFFFFFFFFu,0xFFFFFFFFu,0xFFFFFFFFu,0xFFFFFFFFu,0xFFFFFFFFu,0xFFFFFFFFu,
    0xFFFFFFFFu,0xFFFFFFFFu,0xFFFFFFFFu,0xFFFFFFFFu,0xFFFFFFFFu,0xFFFFFFFFu,0xFFFFFFFFu,0xFFFFFFFFu};
__device__ unsigned g_maxkey[DD] = {0,0,0,0,0,0,0,0,0,0,0,0,0,0,0,0};
__device__ float g_partial[ZGRID];
__device__ unsigned g_ctr = 0;

// ---------------- helpers ----------------
__device__ __forceinline__ unsigned fkey(float f) {
    unsigned u = __float_as_uint(f);
    return (u & 0x80000000u) ? ~u : (u | 0x80000000u);
}
__device__ __forceinline__ float fdec(unsigned k) {
    unsigned u = (k & 0x80000000u) ? (k & 0x7FFFFFFFu) : ~k;
    return __uint_as_float(u);
}
__device__ __forceinline__ float ex2f(float x) {
    float y; asm("ex2.approx.f32 %0, %1;" : "=f"(y) : "f"(x)); return y;
}
__device__ __forceinline__ float lg2f(float x) {
    float y; asm("lg2.approx.f32 %0, %1;" : "=f"(y) : "f"(x)); return y;
}
__device__ __forceinline__ unsigned long long pk2(float lo, float hi) {
    unsigned long long r;
    asm("mov.b64 %0, {%1, %2};" : "=l"(r) : "f"(lo), "f"(hi));
    return r;
}
#define FMA2(d, a, b, c) \
    asm("fma.rn.f32x2 %0, %1, %2, %3;" : "=l"(d) : "l"(a), "l"(b), "l"(c))
#define ADD2(d, a, b) \
    asm("add.rn.f32x2 %0, %1, %2;" : "=l"(d) : "l"(a), "l"(b))
__device__ __forceinline__ void upk2(unsigned long long v, float& lo, float& hi) {
    asm("mov.b64 {%0, %1}, %2;" : "=f"(lo), "=f"(hi) : "l"(v));
}

// ---------------- single fused kernel (2 rows per thread) ----------------
__global__ void __launch_bounds__(TPB, 4) zloss_kernel(const float* __restrict__ met,
                                                       const float* __restrict__ z,
                                                       const float* __restrict__ mu,
                                                       const float* __restrict__ pi,
                                                       const float* __restrict__ rv,
                                                       const float* __restrict__ lambda_mu,
                                                       const float* __restrict__ bv,
                                                       const float* __restrict__ Cv,
                                                       float* __restrict__ out) {
    __shared__ float4 swq[KK * 5];      // per k: w[0..15] (4xf4) + (A, C, lp2, 0)   5 KB
    __shared__ float SZ[RPB * 33];      // staged half-z (32 cols), stride-33        33.8 KB
    __shared__ float spi[KK];
    __shared__ float slse;
    __shared__ float sred[4];
    __shared__ float smn[4][DD], smx[4][DD];
    __shared__ unsigned s_last;

    const int t = threadIdx.x;
    const int lane = t & 31;
    const int wid = t >> 5;

    // ---- prep: softmax(pi) ----
    if (t < KK) spi[t] = pi[t];
    __syncthreads();
    if (t < 32) {
        float a = spi[t], b2 = spi[t + 32];
        float m = fmaxf(a, b2);
#pragma unroll
        for (int off = 16; off; off >>= 1)
            m = fmaxf(m, __shfl_xor_sync(0xffffffffu, m, off));
        float es = __expf(a - m) + __expf(b2 - m);
        float sp = a + b2;
#pragma unroll
        for (int off = 16; off; off >>= 1) {
            es += __shfl_xor_sync(0xffffffffu, es, off);
            sp += __shfl_xor_sync(0xffffffffu, sp, off);
        }
        float lse = m + __logf(es);
        if (t == 0) {
            slse = lse;
            if (blockIdx.x == 0) g_sumlogpi = sp - 64.f * lse;
        }
    }
    __syncthreads();

    // ---- prep: per-k constants into swq ----
    if (t < KK) {
        float lp2 = (spi[t] - slse) * L2E;
        float rk = rv[t];
        float ie = __expf(-rk);
        float sc = L2E * ie;
        const float4* mu4 = reinterpret_cast<const float4*>(mu + t * DD);
        float msq = 0.f;
#pragma unroll
        for (int q = 0; q < 4; q++) {
            float4 mq = mu4[q];
            msq = fmaf(mq.x, mq.x, msq); msq = fmaf(mq.y, mq.y, msq);
            msq = fmaf(mq.z, mq.z, msq); msq = fmaf(mq.w, mq.w, msq);
            swq[t * 5 + q] = make_float4(sc * mq.x, sc * mq.y, sc * mq.z, sc * mq.w);
        }
        float alpha = -0.5f * ie;
        float beta  = -0.5f * 16.f * (rk + (float)DLOG2PI);
        swq[t * 5 + 4] = make_float4(L2E * alpha, L2E * fmaf(alpha, msq, beta), lp2, 0.f);
    }

    // ---- load met rows A (t) and B (t+128); pack ----
    const int rowA = blockIdx.x * RPB + t;
    const int rowB = rowA + TPB;
    const float4* xpa = reinterpret_cast<const float4*>(met + (size_t)rowA * DD);
    const float4* xpb = reinterpret_cast<const float4*>(met + (size_t)rowB * DD);
    float4 a0 = xpa[0], a1 = xpa[1], a2q = xpa[2], a3 = xpa[3];
    float4 b0 = xpb[0], b1 = xpb[1], b2q = xpb[2], b3 = xpb[3];

    float xsa = 0.f, xsb = 0.f;
    xsa = fmaf(a0.x, a0.x, xsa); xsa = fmaf(a0.y, a0.y, xsa); xsa = fmaf(a0.z, a0.z, xsa); xsa = fmaf(a0.w, a0.w, xsa);
    xsa = fmaf(a1.x, a1.x, xsa); xsa = fmaf(a1.y, a1.y, xsa); xsa = fmaf(a1.z, a1.z, xsa); xsa = fmaf(a1.w, a1.w, xsa);
    xsa = fmaf(a2q.x, a2q.x, xsa); xsa = fmaf(a2q.y, a2q.y, xsa); xsa = fmaf(a2q.z, a2q.z, xsa); xsa = fmaf(a2q.w, a2q.w, xsa);
    xsa = fmaf(a3.x, a3.x, xsa); xsa = fmaf(a3.y, a3.y, xsa); xsa = fmaf(a3.z, a3.z, xsa); xsa = fmaf(a3.w, a3.w, xsa);
    xsb = fmaf(b0.x, b0.x, xsb); xsb = fmaf(b0.y, b0.y, xsb); xsb = fmaf(b0.z, b0.z, xsb); xsb = fmaf(b0.w, b0.w, xsb);
    xsb = fmaf(b1.x, b1.x, xsb); xsb = fmaf(b1.y, b1.y, xsb); xsb = fmaf(b1.z, b1.z, xsb); xsb = fmaf(b1.w, b1.w, xsb);
    xsb = fmaf(b2q.x, b2q.x, xsb); xsb = fmaf(b2q.y, b2q.y, xsb); xsb = fmaf(b2q.z, b2q.z, xsb); xsb = fmaf(b2q.w, b2q.w, xsb);
    xsb = fmaf(b3.x, b3.x, xsb); xsb = fmaf(b3.y, b3.y, xsb); xsb = fmaf(b3.z, b3.z, xsb); xsb = fmaf(b3.w, b3.w, xsb);

    unsigned long long xa[8], xb[8];
    xa[0] = pk2(a0.x, a0.y); xa[1] = pk2(a0.z, a0.w);
    xa[2] = pk2(a1.x, a1.y); xa[3] = pk2(a1.z, a1.w);
    xa[4] = pk2(a2q.x, a2q.y); xa[5] = pk2(a2q.z, a2q.w);
    xa[6] = pk2(a3.x, a3.y); xa[7] = pk2(a3.z, a3.w);
    xb[0] = pk2(b0.x, b0.y); xb[1] = pk2(b0.z, b0.w);
    xb[2] = pk2(b1.x, b1.y); xb[3] = pk2(b1.z, b1.w);
    xb[4] = pk2(b2q.x, b2q.y); xb[5] = pk2(b2q.z, b2q.w);
    xb[6] = pk2(b3.x, b3.y); xb[7] = pk2(b3.z, b3.w);

    // ---- two-phase staged main loop ----
    const float4* zg = reinterpret_cast<const float4*>(z) + (size_t)blockIdx.x * (RPB * KK / 4);
    float mva = -3.0e38f, eva = 0.f, eza = 0.f, eua = 0.f, sza = 0.f;
    float mvb = -3.0e38f, evb = 0.f, ezb = 0.f, eub = 0.f, szb = 0.f;

#pragma unroll 1
    for (int half = 0; half < 2; half++) {
        if (half) __syncthreads();
        // stage 32 z-columns for all 256 rows, pre-scaled by log2e
#pragma unroll
        for (int j = 0; j < 16; j++) {
            int idx = j * TPB + t;
            int r = idx >> 3, c = idx & 7;
            float4 v = zg[r * 16 + half * 8 + c];
            float* sp2 = &SZ[r * 33 + c * 4];
            sp2[0] = v.x * L2E; sp2[1] = v.y * L2E; sp2[2] = v.z * L2E; sp2[3] = v.w * L2E;
        }
        __syncthreads();

        const int sa = t * 33;
        const int sb = (t + TPB) * 33;
#pragma unroll 1
        for (int cch = 0; cch < 4; cch++) {
            float vva[8], vvb[8];
#pragma unroll
            for (int i = 0; i < 8; i++) {
                const int kk = cch * 8 + i;
                const int k = half * 32 + kk;
                const ulonglong2* wp = reinterpret_cast<const ulonglong2*>(&swq[k * 5]);
                ulonglong2 q0 = wp[0], q1 = wp[1], q2 = wp[2], q3 = wp[3];
                float4 acp = swq[k * 5 + 4];
                float base_a = fmaf(acp.x, xsa, acp.y);
                float base_b = fmaf(acp.x, xsb, acp.y);
                float z2a = SZ[sa + kk];
                float z2b = SZ[sb + kk];

                unsigned long long A0 = pk2(base_a, z2a), A1 = 0ull;
                unsigned long long B0 = pk2(base_b, z2b), B1 = 0ull;
                FMA2(A0, xa[0], q0.x, A0); FMA2(A1, xa[1], q0.y, A1);
                FMA2(B0, xb[0], q0.x, B0); FMA2(B1, xb[1], q0.y, B1);
                FMA2(A0, xa[2], q1.x, A0); FMA2(A1, xa[3], q1.y, A1);
                FMA2(B0, xb[2], q1.x, B0); FMA2(B1, xb[3], q1.y, B1);
                FMA2(A0, xa[4], q2.x, A0); FMA2(A1, xa[5], q2.y, A1);
                FMA2(B0, xb[4], q2.x, B0); FMA2(B1, xb[5], q2.y, B1);
                FMA2(A0, xa[6], q3.x, A0); FMA2(A1, xa[7], q3.y, A1);
                FMA2(B0, xb[6], q3.x, B0); FMA2(B1, xb[7], q3.y, B1);
                ADD2(A0, A0, A1);
                ADD2(B0, B0, B1);
                float alo, ahi, blo, bhi;
                upk2(A0, alo, ahi); upk2(B0, blo, bhi);
                vva[i] = alo + ahi;                // z2 + logN (log2 units)
                vvb[i] = blo + bhi;

                eza += ex2f(z2a);           ezb += ex2f(z2b);
                eua += ex2f(fmaf(-TAUF, z2a, acp.z));
                eub += ex2f(fmaf(-TAUF, z2b, acp.z));
                sza += z2a;                 szb += z2b;
            }
            float m8a = fmaxf(fmaxf(fmaxf(vva[0], vva[1]), fmaxf(vva[2], vva[3])),
                              fmaxf(fmaxf(vva[4], vva[5]), fmaxf(vva[6], vva[7])));
            float m8b = fmaxf(fmaxf(fmaxf(vvb[0], vvb[1]), fmaxf(vvb[2], vvb[3])),
                              fmaxf(fmaxf(vvb[4], vvb[5]), fmaxf(vvb[6], vvb[7])));
            float mna = fmaxf(mva, m8a);
            float mnb = fmaxf(mvb, m8b);
            float s8a = ex2f(vva[0] - mna) + ex2f(vva[1] - mna)
                      + ex2f(vva[2] - mna) + ex2f(vva[3] - mna)
                      + ex2f(vva[4] - mna) + ex2f(vva[5] - mna)
                      + ex2f(vva[6] - mna) + ex2f(vva[7] - mna);
            float s8b = ex2f(vvb[0] - mnb) + ex2f(vvb[1] - mnb)
                      + ex2f(vvb[2] - mnb) + ex2f(vvb[3] - mnb)
                      + ex2f(vvb[4] - mnb) + ex2f(vvb[5] - mnb)
                      + ex2f(vvb[6] - mnb) + ex2f(vvb[7] - mnb);
            eva = fmaf(eva, ex2f(mva - mna), s8a);  mva = mna;
            evb = fmaf(evb, ex2f(mvb - mnb), s8b);  mvb = mnb;
        }
    }

    float tta = LN2 * (fmaf(63.f, lg2f(eza), fmaf(-64.f, lg2f(eua), mva + lg2f(eva)))
                       - (TAUF + 1.f) * sza);
    float ttb = LN2 * (fmaf(63.f, lg2f(ezb), fmaf(-64.f, lg2f(eub), mvb + lg2f(evb)))
                       - (TAUF + 1.f) * szb);
    float tt = tta + ttb;

    // ---- per-dim min/max over both rows: warp reduce -> block -> atomics ----
#pragma unroll
    for (int i = 0; i < 8; i++) {
        float al, ah, bl, bh;
        upk2(xa[i], al, ah); upk2(xb[i], bl, bh);
        float mn0 = fminf(al, bl), mx0 = fmaxf(al, bl);
        float mn1 = fminf(ah, bh), mx1 = fmaxf(ah, bh);
#pragma unroll
        for (int off = 16; off; off >>= 1) {
            mn0 = fminf(mn0, __shfl_xor_sync(0xffffffffu, mn0, off));
            mx0 = fmaxf(mx0, __shfl_xor_sync(0xffffffffu, mx0, off));
            mn1 = fminf(mn1, __shfl_xor_sync(0xffffffffu, mn1, off));
            mx1 = fmaxf(mx1, __shfl_xor_sync(0xffffffffu, mx1, off));
        }
        if (lane == 0) {
            smn[wid][2 * i] = mn0;     smx[wid][2 * i] = mx0;
            smn[wid][2 * i + 1] = mn1; smx[wid][2 * i + 1] = mx1;
        }
    }

    // ---- block reduce tt ----
#pragma unroll
    for (int off = 16; off; off >>= 1)
        tt += __shfl_xor_sync(0xffffffffu, tt, off);
    if (lane == 0) sred[wid] = tt;
    __syncthreads();

    if (t < DD) {
        float mn = fminf(fminf(smn[0][t], smn[1][t]), fminf(smn[2][t], smn[3][t]));
        atomicMin(&g_minkey[t], fkey(mn));
    } else if (t < 2 * DD) {
        int d = t - DD;
        float mx = fmaxf(fmaxf(smx[0][d], smx[1][d]), fmaxf(smx[2][d], smx[3][d]));
        atomicMax(&g_maxkey[d], fkey(mx));
    }
    __syncthreads();

    if (t == 0) {
        g_partial[blockIdx.x] = sred[0] + sred[1] + sred[2] + sred[3];
        __threadfence();
        unsigned old = atomicAdd(&g_ctr, 1u);
        s_last = (old == (unsigned)(ZGRID - 1)) ? 1u : 0u;
    }
    __syncthreads();
    if (!s_last) return;

    // ================= last block: final scalar epilogue =================
    __threadfence();
    float* shR = spi;                      // reuse
    if (t < DD) shR[t] = fdec(g_maxkey[t]) - fdec(g_minkey[t]);
    __syncthreads();

    double R2 = 0.0;
#pragma unroll
    for (int d = 0; d < DD; d++) R2 += (double)shR[d] * (double)shR[d];
    const double cc = 5.0, gg = 4.0;
    const double Gd = cc / (50.0 * gg) * sqrt(R2);
    const double lgG = (double)__logf((float)Gd);

    const double LG_HALF = 0.5723649429247001;       // lgamma(0.5)
    const double LG_C    = 3.1780538303479458;       // lgamma(5)
    const double LG_G    = 1.791759469228055;        // lgamma(4)
    const double LG_64   = 201.00931639928152;       // lgamma(64)
    const double LN_HALF = -0.6931471805599453;
    const double LN_TENTH = -2.302585092994046;

    double acc = 0.0;
    for (int i = t; i < KK * DD; i += TPB) {
        int d = i & (DD - 1);
        float lam = lambda_mu[d];
        float var = lam * lam * shR[d];
        float diff = mu[i] - bv[i];
        float bb = bv[i];
        acc += (double)(0.5f * diff * diff / var) + (double)(0.5f * bb * bb);
    }
    for (int d = t; d < DD; d += TPB) {
        float lam = lambda_mu[d];
        float var = lam * lam * shR[d];
        acc += 0.5 * (double)KK * (double)__logf(var);
        acc -= 0.5 * LN_HALF - LG_HALF - 0.5 * (double)lam - 0.5 * (double)__expf(lam);
    }
    for (int k = t; k < KK; k += TPB) {
        float rk = rv[k], Ck = Cv[k];
        acc -= cc * (double)__logf(Ck) - (cc - 1.0) * (double)rk
               - (double)Ck * (double)__expf(-rk) - LG_C;
        acc -= gg * lgG - (gg - 1.0) * (double)Ck
               - Gd * (double)__expf(-Ck) - LG_G;
    }
    const float4* p4 = reinterpret_cast<const float4*>(g_partial);
    for (int i = t; i < ZGRID / 4; i += TPB) {
        float4 v = p4[i];
        acc -= (double)v.x + (double)v.y + (double)v.z + (double)v.w;
    }

    double* dred = reinterpret_cast<double*>(SZ);    // overlay (SZ no longer needed)
    dred[t] = acc;
    __syncthreads();
#pragma unroll
    for (int s = 64; s; s >>= 1) {
        if (t < s) dred[t] += dred[t + s];
        __syncthreads();
    }
    if (t == 0) {
        double total = dred[0];
        double sumlp = (double)g_sumlogpi;
        double G0 = LG_64 + 63.0 * LN_TENTH + sumlp;          // per-row constant in con
        total -= (double)NN * G0;                             // z-loss constant part
        total += (63.0 / 64.0) * sumlp;                       // pi_loss
        total += (double)KK * 0.5 * (double)DD * DLOG2PI;     // mu_loss const
        total += 0.5 * (double)KK * (double)DD * DLOG2PI;     // b_loss const
        out[0] = (float)total;
        atomicExch(&g_ctr, 0u);                               // reset for graph replay
    }
}

// ---------------- launch ----------------
extern "C" void kernel_launch(void* const* d_in, const int* in_sizes, int n_in,
                              void* d_out, int out_size) {
    const float* met = (const float*)d_in[0];
    const float* mu  = (const float*)d_in[1];
    const float* pi  = (const float*)d_in[2];
    const float* lam = (const float*)d_in[3];
    const float* b   = (const float*)d_in[4];
    const float* C   = (const float*)d_in[5];
    const float* r   = (const float*)d_in[6];
    const float* z   = (const float*)d_in[7];
    (void)in_sizes; (void)n_in; (void)out_size;

    zloss_kernel<<<ZGRID, TPB>>>(met, z, mu, pi, r, lam, b, C, (float*)d_out);
}

// round 10
// speedup vs baseline: 17.3062x; 1.0049x over previous
#include <cuda_runtime.h>
#include <math.h>
#include <stdint.h>

#define NN 262144
#define DD 16
#define KK 64
#define TAUF 0.1f
#define DLOG2PI 1.8378770664093454835
#define L2E 1.4426950408889634f
#define LN2 0.6931471805599453f

#define TPB 128            // threads per block
#define RPB 256            // rows per block (2 rows per thread)
#define ZGRID (NN / RPB)   // 1024

// ---------------- device globals ----------------
__device__ float g_sumlogpi;
__device__ unsigned g_minkey[DD] = {
    0xFFFFFFFFu,0xFFFFFFFFu,0xFFFFFFFFu,0xFFFFFFFFu,0xFFFFFFFFu,0xFFFFFFFFu,0xFFFFFFFFu,0xFFFFFFFFu,
    0xFFFFFFFFu,0xFFFFFFFFu,0xFFFFFFFFu,0xFFFFFFFFu,0xFFFFFFFFu,0xFFFFFFFFu,0xFFFFFFFFu,0xFFFFFFFFu};
__device__ unsigned g_maxkey[DD] = {0,0,0,0,0,0,0,0,0,0,0,0,0,0,0,0};
__device__ float g_partial[ZGRID];
__device__ unsigned g_ctr = 0;

// ---------------- helpers ----------------
__device__ __forceinline__ unsigned fkey(float f) {
    unsigned u = __float_as_uint(f);
    return (u & 0x80000000u) ? ~u : (u | 0x80000000u);
}
__device__ __forceinline__ float fdec(unsigned k) {
    unsigned u = (k & 0x80000000u) ? (k & 0x7FFFFFFFu) : ~k;
    return __uint_as_float(u);
}
__device__ __forceinline__ float ex2f(float x) {
    float y; asm("ex2.approx.f32 %0, %1;" : "=f"(y) : "f"(x)); return y;
}
__device__ __forceinline__ float lg2f(float x) {
    float y; asm("lg2.approx.f32 %0, %1;" : "=f"(y) : "f"(x)); return y;
}
__device__ __forceinline__ unsigned long long pk2(float lo, float hi) {
    unsigned long long r;
    asm("mov.b64 %0, {%1, %2};" : "=l"(r) : "f"(lo), "f"(hi));
    return r;
}
#define FMA2(d, a, b, c) \
    asm("fma.rn.f32x2 %0, %1, %2, %3;" : "=l"(d) : "l"(a), "l"(b), "l"(c))
#define ADD2(d, a, b) \
    asm("add.rn.f32x2 %0, %1, %2;" : "=l"(d) : "l"(a), "l"(b))
__device__ __forceinline__ void upk2(unsigned long long v, float& lo, float& hi) {
    asm("mov.b64 {%0, %1}, %2;" : "=f"(lo), "=f"(hi) : "l"(v));
}

// ---------------- single fused kernel (2 rows per thread) ----------------
__global__ void __launch_bounds__(TPB, 4) zloss_kernel(const float* __restrict__ met,
                                                       const float* __restrict__ z,
                                                       const float* __restrict__ mu,
                                                       const float* __restrict__ pi,
                                                       const float* __restrict__ rv,
                                                       const float* __restrict__ lambda_mu,
                                                       const float* __restrict__ bv,
                                                       const float* __restrict__ Cv,
                                                       float* __restrict__ out) {
    __shared__ float4 swq[KK * 5];      // per k: w[0..15] (4xf4) + (A, C, lp2, 0)   5 KB
    __shared__ float SZ[RPB * 33];      // staged half-z (32 cols), stride-33        33.8 KB
    __shared__ float spi[KK];
    __shared__ float slse;
    __shared__ float sred[4];
    __shared__ float smn[4][DD], smx[4][DD];
    __shared__ unsigned s_last;

    const int t = threadIdx.x;
    const int lane = t & 31;
    const int wid = t >> 5;

    // ---- prep: softmax(pi) ----
    if (t < KK) spi[t] = pi[t];
    __syncthreads();
    if (t < 32) {
        float a = spi[t], b2 = spi[t + 32];
        float m = fmaxf(a, b2);
#pragma unroll
        for (int off = 16; off; off >>= 1)
            m = fmaxf(m, __shfl_xor_sync(0xffffffffu, m, off));
        float es = __expf(a - m) + __expf(b2 - m);
        float sp = a + b2;
#pragma unroll
        for (int off = 16; off; off >>= 1) {
            es += __shfl_xor_sync(0xffffffffu, es, off);
            sp += __shfl_xor_sync(0xffffffffu, sp, off);
        }
        float lse = m + __logf(es);
        if (t == 0) {
            slse = lse;
            if (blockIdx.x == 0) g_sumlogpi = sp - 64.f * lse;
        }
    }
    __syncthreads();

    // ---- prep: per-k constants into swq ----
    if (t < KK) {
        float lp2 = (spi[t] - slse) * L2E;
        float rk = rv[t];
        float ie = __expf(-rk);
        float sc = L2E * ie;
        const float4* mu4 = reinterpret_cast<const float4*>(mu + t * DD);
        float msq = 0.f;
#pragma unroll
        for (int q = 0; q < 4; q++) {
            float4 mq = mu4[q];
            msq = fmaf(mq.x, mq.x, msq); msq = fmaf(mq.y, mq.y, msq);
            msq = fmaf(mq.z, mq.z, msq); msq = fmaf(mq.w, mq.w, msq);
            swq[t * 5 + q] = make_float4(sc * mq.x, sc * mq.y, sc * mq.z, sc * mq.w);
        }
        float alpha = -0.5f * ie;
        float beta  = -0.5f * 16.f * (rk + (float)DLOG2PI);
        swq[t * 5 + 4] = make_float4(L2E * alpha, L2E * fmaf(alpha, msq, beta), lp2, 0.f);
    }

    // ---- load met rows A (t) and B (t+128); pack ----
    const int rowA = blockIdx.x * RPB + t;
    const int rowB = rowA + TPB;
    const float4* xpa = reinterpret_cast<const float4*>(met + (size_t)rowA * DD);
    const float4* xpb = reinterpret_cast<const float4*>(met + (size_t)rowB * DD);
    float4 a0 = xpa[0], a1 = xpa[1], a2q = xpa[2], a3 = xpa[3];
    float4 b0 = xpb[0], b1 = xpb[1], b2q = xpb[2], b3 = xpb[3];

    float xsa = 0.f, xsb = 0.f;
    xsa = fmaf(a0.x, a0.x, xsa); xsa = fmaf(a0.y, a0.y, xsa); xsa = fmaf(a0.z, a0.z, xsa); xsa = fmaf(a0.w, a0.w, xsa);
    xsa = fmaf(a1.x, a1.x, xsa); xsa = fmaf(a1.y, a1.y, xsa); xsa = fmaf(a1.z, a1.z, xsa); xsa = fmaf(a1.w, a1.w, xsa);
    xsa = fmaf(a2q.x, a2q.x, xsa); xsa = fmaf(a2q.y, a2q.y, xsa); xsa = fmaf(a2q.z, a2q.z, xsa); xsa = fmaf(a2q.w, a2q.w, xsa);
    xsa = fmaf(a3.x, a3.x, xsa); xsa = fmaf(a3.y, a3.y, xsa); xsa = fmaf(a3.z, a3.z, xsa); xsa = fmaf(a3.w, a3.w, xsa);
    xsb = fmaf(b0.x, b0.x, xsb); xsb = fmaf(b0.y, b0.y, xsb); xsb = fmaf(b0.z, b0.z, xsb); xsb = fmaf(b0.w, b0.w, xsb);
    xsb = fmaf(b1.x, b1.x, xsb); xsb = fmaf(b1.y, b1.y, xsb); xsb = fmaf(b1.z, b1.z, xsb); xsb = fmaf(b1.w, b1.w, xsb);
    xsb = fmaf(b2q.x, b2q.x, xsb); xsb = fmaf(b2q.y, b2q.y, xsb); xsb = fmaf(b2q.z, b2q.z, xsb); xsb = fmaf(b2q.w, b2q.w, xsb);
    xsb = fmaf(b3.x, b3.x, xsb); xsb = fmaf(b3.y, b3.y, xsb); xsb = fmaf(b3.z, b3.z, xsb); xsb = fmaf(b3.w, b3.w, xsb);

    unsigned long long xa[8], xb[8];
    xa[0] = pk2(a0.x, a0.y); xa[1] = pk2(a0.z, a0.w);
    xa[2] = pk2(a1.x, a1.y); xa[3] = pk2(a1.z, a1.w);
    xa[4] = pk2(a2q.x, a2q.y); xa[5] = pk2(a2q.z, a2q.w);
    xa[6] = pk2(a3.x, a3.y); xa[7] = pk2(a3.z, a3.w);
    xb[0] = pk2(b0.x, b0.y); xb[1] = pk2(b0.z, b0.w);
    xb[2] = pk2(b1.x, b1.y); xb[3] = pk2(b1.z, b1.w);
    xb[4] = pk2(b2q.x, b2q.y); xb[5] = pk2(b2q.z, b2q.w);
    xb[6] = pk2(b3.x, b3.y); xb[7] = pk2(b3.z, b3.w);

    // ---- two-phase staged main loop ----
    const float4* zg = reinterpret_cast<const float4*>(z) + (size_t)blockIdx.x * (RPB * KK / 4);
    float mva = -3.0e38f, eva = 0.f, eza = 0.f, eua = 0.f, sza = 0.f;
    float mvb = -3.0e38f, evb = 0.f, ezb = 0.f, eub = 0.f, szb = 0.f;

#pragma unroll 1
    for (int half = 0; half < 2; half++) {
        if (half) __syncthreads();
        // stage 32 z-columns for all 256 rows, pre-scaled by log2e
#pragma unroll
        for (int j = 0; j < 16; j++) {
            int idx = j * TPB + t;
            int r = idx >> 3, c = idx & 7;
            float4 v = zg[r * 16 + half * 8 + c];
            float* sp2 = &SZ[r * 33 + c * 4];
            sp2[0] = v.x * L2E; sp2[1] = v.y * L2E; sp2[2] = v.z * L2E; sp2[3] = v.w * L2E;
        }
        __syncthreads();

        const int sa = t * 33;
        const int sb = (t + TPB) * 33;
#pragma unroll 1
        for (int cch = 0; cch < 4; cch++) {
            float vva[8], vvb[8];
#pragma unroll
            for (int i = 0; i < 8; i++) {
                const int kk = cch * 8 + i;
                const int k = half * 32 + kk;
                const ulonglong2* wp = reinterpret_cast<const ulonglong2*>(&swq[k * 5]);
                ulonglong2 q0 = wp[0], q1 = wp[1], q2 = wp[2], q3 = wp[3];
                float4 acp = swq[k * 5 + 4];
                float base_a = fmaf(acp.x, xsa, acp.y);
                float base_b = fmaf(acp.x, xsb, acp.y);
                float z2a = SZ[sa + kk];
                float z2b = SZ[sb + kk];

                unsigned long long A0 = pk2(base_a, z2a), A1 = 0ull;
                unsigned long long B0 = pk2(base_b, z2b), B1 = 0ull;
                FMA2(A0, xa[0], q0.x, A0); FMA2(A1, xa[1], q0.y, A1);
                FMA2(B0, xb[0], q0.x, B0); FMA2(B1, xb[1], q0.y, B1);
                FMA2(A0, xa[2], q1.x, A0); FMA2(A1, xa[3], q1.y, A1);
                FMA2(B0, xb[2], q1.x, B0); FMA2(B1, xb[3], q1.y, B1);
                FMA2(A0, xa[4], q2.x, A0); FMA2(A1, xa[5], q2.y, A1);
                FMA2(B0, xb[4], q2.x, B0); FMA2(B1, xb[5], q2.y, B1);
                FMA2(A0, xa[6], q3.x, A0); FMA2(A1, xa[7], q3.y, A1);
                FMA2(B0, xb[6], q3.x, B0); FMA2(B1, xb[7], q3.y, B1);
                ADD2(A0, A0, A1);
                ADD2(B0, B0, B1);
                float alo, ahi, blo, bhi;
                upk2(A0, alo, ahi); upk2(B0, blo, bhi);
                vva[i] = alo + ahi;                // z2 + logN (log2 units)
                vvb[i] = blo + bhi;

                eza += ex2f(z2a);           ezb += ex2f(z2b);
                eua += ex2f(fmaf(-TAUF, z2a, acp.z));
                eub += ex2f(fmaf(-TAUF, z2b, acp.z));
                sza += z2a;                 szb += z2b;
            }
            float m8a = fmaxf(fmaxf(fmaxf(vva[0], vva[1]), fmaxf(vva[2], vva[3])),
                              fmaxf(fmaxf(vva[4], vva[5]), fmaxf(vva[6], vva[7])));
            float m8b = fmaxf(fmaxf(fmaxf(vvb[0], vvb[1]), fmaxf(vvb[2], vvb[3])),
                              fmaxf(fmaxf(vvb[4], vvb[5]), fmaxf(vvb[6], vvb[7])));
            float mna = fmaxf(mva, m8a);
            float mnb = fmaxf(mvb, m8b);
            float s8a = ex2f(vva[0] - mna) + ex2f(vva[1] - mna)
                      + ex2f(vva[2] - mna) + ex2f(vva[3] - mna)
                      + ex2f(vva[4] - mna) + ex2f(vva[5] - mna)
                      + ex2f(vva[6] - mna) + ex2f(vva[7] - mna);
            float s8b = ex2f(vvb[0] - mnb) + ex2f(vvb[1] - mnb)
                      + ex2f(vvb[2] - mnb) + ex2f(vvb[3] - mnb)
                      + ex2f(vvb[4] - mnb) + ex2f(vvb[5] - mnb)
                      + ex2f(vvb[6] - mnb) + ex2f(vvb[7] - mnb);
            eva = fmaf(eva, ex2f(mva - mna), s8a);  mva = mna;
            evb = fmaf(evb, ex2f(mvb - mnb), s8b);  mvb = mnb;
        }
    }

    float tta = LN2 * (fmaf(63.f, lg2f(eza), fmaf(-64.f, lg2f(eua), mva + lg2f(eva)))
                       - (TAUF + 1.f) * sza);
    float ttb = LN2 * (fmaf(63.f, lg2f(ezb), fmaf(-64.f, lg2f(eub), mvb + lg2f(evb)))
                       - (TAUF + 1.f) * szb);
    float tt = tta + ttb;

    // ---- per-dim min/max over both rows: warp reduce -> block -> atomics ----
#pragma unroll
    for (int i = 0; i < 8; i++) {
        float al, ah, bl, bh;
        upk2(xa[i], al, ah); upk2(xb[i], bl, bh);
        float mn0 = fminf(al, bl), mx0 = fmaxf(al, bl);
        float mn1 = fminf(ah, bh), mx1 = fmaxf(ah, bh);
#pragma unroll
        for (int off = 16; off; off >>= 1) {
            mn0 = fminf(mn0, __shfl_xor_sync(0xffffffffu, mn0, off));
            mx0 = fmaxf(mx0, __shfl_xor_sync(0xffffffffu, mx0, off));
            mn1 = fminf(mn1, __shfl_xor_sync(0xffffffffu, mn1, off));
            mx1 = fmaxf(mx1, __shfl_xor_sync(0xffffffffu, mx1, off));
        }
        if (lane == 0) {
            smn[wid][2 * i] = mn0;     smx[wid][2 * i] = mx0;
            smn[wid][2 * i + 1] = mn1; smx[wid][2 * i + 1] = mx1;
        }
    }

    // ---- block reduce tt ----
#pragma unroll
    for (int off = 16; off; off >>= 1)
        tt += __shfl_xor_sync(0xffffffffu, tt, off);
    if (lane == 0) sred[wid] = tt;
    __syncthreads();

    if (t < DD) {
        float mn = fminf(fminf(smn[0][t], smn[1][t]), fminf(smn[2][t], smn[3][t]));
        atomicMin(&g_minkey[t], fkey(mn));
    } else if (t < 2 * DD) {
        int d = t - DD;
        float mx = fmaxf(fmaxf(smx[0][d], smx[1][d]), fmaxf(smx[2][d], smx[3][d]));
        atomicMax(&g_maxkey[d], fkey(mx));
    }
    __syncthreads();

    if (t == 0) {
        g_partial[blockIdx.x] = sred[0] + sred[1] + sred[2] + sred[3];
        __threadfence();
        unsigned old = atomicAdd(&g_ctr, 1u);
        s_last = (old == (unsigned)(ZGRID - 1)) ? 1u : 0u;
    }
    __syncthreads();
    if (!s_last) return;

    // ================= last block: final scalar epilogue =================
    __threadfence();
    float* shR = spi;                      // reuse
    if (t < DD) shR[t] = fdec(g_maxkey[t]) - fdec(g_minkey[t]);
    __syncthreads();

    double R2 = 0.0;
#pragma unroll
    for (int d = 0; d < DD; d++) R2 += (double)shR[d] * (double)shR[d];
    const double cc = 5.0, gg = 4.0;
    const double Gd = cc / (50.0 * gg) * sqrt(R2);
    const double lgG = (double)__logf((float)Gd);

    const double LG_HALF = 0.5723649429247001;       // lgamma(0.5)
    const double LG_C    = 3.1780538303479458;       // lgamma(5)
    const double LG_G    = 1.791759469228055;        // lgamma(4)
    const double LG_64   = 201.00931639928152;       // lgamma(64)
    const double LN_HALF = -0.6931471805599453;
    const double LN_TENTH = -2.302585092994046;

    double acc = 0.0;
    for (int i = t; i < KK * DD; i += TPB) {
        int d = i & (DD - 1);
        float lam = lambda_mu[d];
        float var = lam * lam * shR[d];
        float diff = mu[i] - bv[i];
        float bb = bv[i];
        acc += (double)(0.5f * diff * diff / var) + (double)(0.5f * bb * bb);
    }
    for (int d = t; d < DD; d += TPB) {
        float lam = lambda_mu[d];
        float var = lam * lam * shR[d];
        acc += 0.5 * (double)KK * (double)__logf(var);
        acc -= 0.5 * LN_HALF - LG_HALF - 0.5 * (double)lam - 0.5 * (double)__expf(lam);
    }
    for (int k = t; k < KK; k += TPB) {
        float rk = rv[k], Ck = Cv[k];
        acc -= cc * (double)__logf(Ck) - (cc - 1.0) * (double)rk
               - (double)Ck * (double)__expf(-rk) - LG_C;
        acc -= gg * lgG - (gg - 1.0) * (double)Ck
               - Gd * (double)__expf(-Ck) - LG_G;
    }
    const float4* p4 = reinterpret_cast<const float4*>(g_partial);
    for (int i = t; i < ZGRID / 4; i += TPB) {
        float4 v = p4[i];
        acc -= (double)v.x + (double)v.y + (double)v.z + (double)v.w;
    }

    double* dred = reinterpret_cast<double*>(SZ);    // overlay (SZ no longer needed)
    dred[t] = acc;
    __syncthreads();
#pragma unroll
    for (int s = 64; s; s >>= 1) {
        if (t < s) dred[t] += dred[t + s];
        __syncthreads();
    }
    if (t == 0) {
        double total = dred[0];
        double sumlp = (double)g_sumlogpi;
        double G0 = LG_64 + 63.0 * LN_TENTH + sumlp;          // per-row constant in con
        total -= (double)NN * G0;                             // z-loss constant part
        total += (63.0 / 64.0) * sumlp;                       // pi_loss
        total += (double)KK * 0.5 * (double)DD * DLOG2PI;     // mu_loss const
        total += 0.5 * (double)KK * (double)DD * DLOG2PI;     // b_loss const
        out[0] = (float)total;
        atomicExch(&g_ctr, 0u);                               // reset for graph replay
    }
}

// ---------------- launch ----------------
extern "C" void kernel_launch(void* const* d_in, const int* in_sizes, int n_in,
                              void* d_out, int out_size) {
    const float* met = (const float*)d_in[0];
    const float* mu  = (const float*)d_in[1];
    const float* pi  = (const float*)d_in[2];
    const float* lam = (const float*)d_in[3];
    const float* b   = (const float*)d_in[4];
    const float* C   = (const float*)d_in[5];
    const float* r   = (const float*)d_in[6];
    const float* z   = (const float*)d_in[7];
    (void)in_sizes; (void)n_in; (void)out_size;

    zloss_kernel<<<ZGRID, TPB>>>(met, z, mu, pi, r, lam, b, C, (float*)d_out);
}